// round 3
// baseline (speedup 1.0000x reference)
#include <cuda_runtime.h>
#include <cuda_bf16.h>
#include <math.h>

#define NN   768
#define KK   32
#define CS   384
#define CZ   128
#define CG   16
#define NH   4
#define DHD  32
#define EE   (NN*KK)
#define NRBF 64

// ---------------- scratch (device globals; allocation-free) ----------------
__device__ float g_nl[NN*CG];
__device__ float g_nr[NN*CG];
__device__ float g_z[(size_t)EE*CZ];            // layernormed edge features
__device__ float g_qkvo[(size_t)EE*512];        // cols: q[0:128) k[128:256) v[256:384) sig(og)[384:512)
__device__ float g_bias[(size_t)NN*NH*KK*KK];   // [n][h][i][j]
__device__ float g_og[(size_t)EE*CZ];           // gated attention output
__device__ float g_wcat[CZ*512];
__device__ float g_bcat[512];

// ---------------- kernel: concat projection weights ----------------
__global__ void k_concat(const float* __restrict__ wq, const float* __restrict__ bq,
                         const float* __restrict__ wkv, const float* __restrict__ bkv,
                         const float* __restrict__ wog, const float* __restrict__ bog)
{
    int c = blockIdx.x;          // 0..127
    int t = threadIdx.x;         // 0..511
    float v;
    if (t < 128)       v = wq[c*128 + t];
    else if (t < 384)  v = wkv[c*256 + (t-128)];
    else               v = wog[c*128 + (t-384)];
    g_wcat[c*512 + t] = v;
    if (c == 0) {
        float b;
        if (t < 128)      b = bq[t];
        else if (t < 384) b = bkv[t-128];
        else              b = bog[t-384];
        g_bcat[t] = b;
    }
}

// ---------------- kernel: node left/right projections (tiny) ----------------
__global__ void k_nlr(const float* __restrict__ nf,
                      const float* __restrict__ wl, const float* __restrict__ bl,
                      const float* __restrict__ wr, const float* __restrict__ br)
{
    int n = blockIdx.x;
    int t = threadIdx.x;          // 32 threads
    int c0 = t & 15;
    const float* w = (t < 16) ? wl : wr;
    float acc = (t < 16) ? bl[c0] : br[c0];
    const float* row = nf + (size_t)n*CS;
    #pragma unroll 4
    for (int c = 0; c < CS; c++) acc += __ldg(row + c) * __ldg(w + c*CG + c0);
    if (t < 16) g_nl[n*CG + c0] = acc;
    else        g_nr[n*CG + c0] = acc;
}

// ---------------- kernel: LayerNorm over c_z ----------------
__global__ __launch_bounds__(128) void k_ln(const float* __restrict__ ef,
                                            const float* __restrict__ gam,
                                            const float* __restrict__ bet)
{
    int e = blockIdx.x;
    int t = threadIdx.x;
    float x = ef[(size_t)e*CZ + t];
    float s = x, s2 = x*x;
    #pragma unroll
    for (int o = 16; o > 0; o >>= 1) {
        s  += __shfl_xor_sync(0xffffffffu, s,  o);
        s2 += __shfl_xor_sync(0xffffffffu, s2, o);
    }
    __shared__ float ws[4], ws2[4];
    int w = t >> 5;
    if ((t & 31) == 0) { ws[w] = s; ws2[w] = s2; }
    __syncthreads();
    s  = ws[0]  + ws[1]  + ws[2]  + ws[3];
    s2 = ws2[0] + ws2[1] + ws2[2] + ws2[3];
    float mu  = s  * (1.f/128.f);
    float var = s2 * (1.f/128.f) - mu*mu;
    float inv = rsqrtf(var + 1e-5f);
    g_z[(size_t)e*CZ + t] = (x - mu) * inv * gam[t] + bet[t];
}

// ---------------- kernel: tiled SGEMM  C[M,n] = A[M,128] @ B[128,n] + bias ----------------
// BM=128, BN=64, BK=32, 256 threads, 8x4 microtile. ldc == ldb == total n.
__global__ __launch_bounds__(256) void k_gemm(const float* __restrict__ A,
                                              const float* __restrict__ B,
                                              float* __restrict__ C,
                                              int ldb,
                                              const float* __restrict__ bias,
                                              int sigStart)
{
    __shared__ float As[32*132];
    __shared__ float Bs[32*68];
    int tid = threadIdx.x;
    int row0 = blockIdx.x * 128;
    int n0   = blockIdx.y * 64;
    int tx = tid & 15;       // 4 cols each
    int ty = tid >> 4;       // 8 rows each
    float acc[8][4] = {};
    for (int k0 = 0; k0 < 128; k0 += 32) {
        #pragma unroll
        for (int it = 0; it < 4; it++) {
            int idx = tid + it*256;             // 0..1023
            int r = idx >> 3, kc = idx & 7;
            float4 v = *(const float4*)(A + (size_t)(row0 + r)*128 + k0 + kc*4);
            As[(kc*4+0)*132 + r] = v.x;
            As[(kc*4+1)*132 + r] = v.y;
            As[(kc*4+2)*132 + r] = v.z;
            As[(kc*4+3)*132 + r] = v.w;
        }
        #pragma unroll
        for (int it = 0; it < 2; it++) {
            int idx = tid + it*256;             // 0..511
            int r = idx >> 4, nc = idx & 15;
            float4 v = *(const float4*)(B + (size_t)(k0 + r)*ldb + n0 + nc*4);
            *(float4*)(Bs + r*68 + nc*4) = v;
        }
        __syncthreads();
        #pragma unroll
        for (int kk = 0; kk < 32; kk++) {
            float4 a0 = *(const float4*)(As + kk*132 + ty*8);
            float4 a1 = *(const float4*)(As + kk*132 + ty*8 + 4);
            float4 b0 = *(const float4*)(Bs + kk*68 + tx*4);
            float a[8] = {a0.x,a0.y,a0.z,a0.w,a1.x,a1.y,a1.z,a1.w};
            float b[4] = {b0.x,b0.y,b0.z,b0.w};
            #pragma unroll
            for (int m = 0; m < 8; m++)
                #pragma unroll
                for (int nq = 0; nq < 4; nq++)
                    acc[m][nq] += a[m]*b[nq];
        }
        __syncthreads();
    }
    #pragma unroll
    for (int m = 0; m < 8; m++) {
        int row = row0 + ty*8 + m;
        #pragma unroll
        for (int nq = 0; nq < 4; nq++) {
            int col = n0 + tx*4 + nq;
            float v = acc[m][nq] + bias[col];
            if (col >= sigStart) v = __fdividef(1.f, 1.f + __expf(-v));
            C[(size_t)row*ldb + col] = v;
        }
    }
}

// ---------------- kernel: triangle bias (the heavy one) ----------------
// Per node n: gate[n,i,j,c] = sum_{k,l} e1[i,k] e2[j,l] W[k*16+l, c]  (bilinear
// factorization through M[c][j][k] = sum_l e2[j,l] W[k*16+l, c], channel-chunked
// by 16), db via 9-tap truncated RBF, bias[n,h,i,j] = sum_c sigmoid(gate)*db*wtob[c,h].
// All shared memory STATIC and < 48KB.
__global__ __launch_bounds__(512) void k_tri(const int* __restrict__ ei,   // int32! (JAX x64 off)
                                             const float* __restrict__ trans,
                                             const float* __restrict__ W,       // w_bgate [256,128]
                                             const float* __restrict__ b_bgate,
                                             const float* __restrict__ wdist,   // [64,128]
                                             const float* __restrict__ b_dist,
                                             const float* __restrict__ wtob)    // [128,4]
{
    __shared__ float s_e1[32*16];      // [i][k]
    __shared__ float s_e2t[16*32];     // [l][j]
    __shared__ float s_t[32*4];
    __shared__ float s_wt[128*4];      // [c][h]
    __shared__ float s_wdc[16*68];     // [c within chunk][r]
    __shared__ float s_M[16*32*17];    // [c within chunk][j][k], pad 17
    __shared__ int   s_src[32];

    int n = blockIdx.x;
    int tid = threadIdx.x;

    if (tid < 32) s_src[tid] = ei[n*KK + tid];   // edge_index row 0 (src), int32
    __syncthreads();
    {
        int i = tid >> 4, k = tid & 15;       // 512 threads = 32 i x 16 k
        int s0 = s_src[i];
        s_e1[i*16 + k]  = g_nl[s0*CG + k];
        s_e2t[k*32 + i] = g_nr[s0*CG + k];    // transposed: [l][j]
        s_wt[tid] = wtob[tid];                // [128,4] row-major = [c][h]
    }
    if (tid < 96) { int i = tid/3, c = tid - i*3; s_t[i*4+c] = trans[s_src[i]*3 + c]; }
    __syncthreads();

    // ---- per-thread (i,j) pair assignment for phase B ----
    int j  = tid >> 4;              // 0..31
    int ib = (tid & 15) * 2;        // i in {ib, ib+1}

    int   r0[2];
    float rbfv[2][9];
    float e1r[2][16];
    #pragma unroll
    for (int ii = 0; ii < 2; ii++) {
        int i = ib + ii;
        float dx = s_t[i*4+0] - s_t[j*4+0] + 1e-8f;
        float dy = s_t[i*4+1] - s_t[j*4+1] + 1e-8f;
        float dz = s_t[i*4+2] - s_t[j*4+2] + 1e-8f;
        float dd = sqrtf(dx*dx + dy*dy + dz*dz);
        int rc = (int)rintf(dd * (63.0f/20.0f));
        int rr0 = rc - 4; rr0 = max(rr0, 0); rr0 = min(rr0, 55);
        r0[ii] = rr0;
        #pragma unroll
        for (int r = 0; r < 9; r++) {
            float mu = (float)(rr0 + r) * (20.0f/63.0f);
            float x = (dd - mu) * 3.2f;           // 1/sigma, sigma = 20/64
            rbfv[ii][r] = __expf(-x*x);
        }
        #pragma unroll
        for (int k = 0; k < 16; k++) e1r[ii][k] = s_e1[i*16 + k];
    }

    // ---- phase A thread assignment ----
    int jA = tid & 31;              // 0..31
    int kA = tid >> 5;              // 0..15  (warp-uniform)

    float bacc[2][4] = {};

    for (int ch = 0; ch < 8; ch++) {
        int cb = ch * 16;
        // stage wdist chunk: s_wdc[c][r] = wdist[r*128 + cb + c]
        #pragma unroll
        for (int it = 0; it < 2; it++) {
            int p = tid + it*512;               // 0..1023
            int r = p >> 4, c = p & 15;
            s_wdc[c*68 + r] = __ldg(wdist + r*128 + cb + c);
        }
        // phase A: M[c][j][k] = sum_l e2[j,l] * W[(k*16+l)*128 + cb+c]
        {
            float a[16];
            #pragma unroll
            for (int c = 0; c < 16; c++) a[c] = 0.f;
            #pragma unroll
            for (int l = 0; l < 16; l++) {
                float e2v = s_e2t[l*32 + jA];
                const float4* Wp = (const float4*)(W + (size_t)(kA*16 + l)*128 + cb);
                float4 w0 = __ldg(Wp+0), w1 = __ldg(Wp+1), w2 = __ldg(Wp+2), w3 = __ldg(Wp+3);
                a[0]  += e2v*w0.x; a[1]  += e2v*w0.y; a[2]  += e2v*w0.z; a[3]  += e2v*w0.w;
                a[4]  += e2v*w1.x; a[5]  += e2v*w1.y; a[6]  += e2v*w1.z; a[7]  += e2v*w1.w;
                a[8]  += e2v*w2.x; a[9]  += e2v*w2.y; a[10] += e2v*w2.z; a[11] += e2v*w2.w;
                a[12] += e2v*w3.x; a[13] += e2v*w3.y; a[14] += e2v*w3.z; a[15] += e2v*w3.w;
            }
            #pragma unroll
            for (int c = 0; c < 16; c++) s_M[(c*32 + jA)*17 + kA] = a[c];
        }
        __syncthreads();
        // phase B
        #pragma unroll 1
        for (int cc = 0; cc < 16; cc++) {
            int c = cb + cc;
            float Mk[16];
            #pragma unroll
            for (int k = 0; k < 16; k++) Mk[k] = s_M[(cc*32 + j)*17 + k];
            float bg = __ldg(b_bgate + c);
            float bd = __ldg(b_dist + c);
            float w0 = s_wt[c*4+0], w1 = s_wt[c*4+1], w2 = s_wt[c*4+2], w3 = s_wt[c*4+3];
            #pragma unroll
            for (int ii = 0; ii < 2; ii++) {
                float g = bg;
                #pragma unroll
                for (int k = 0; k < 16; k++) g += e1r[ii][k] * Mk[k];
                float sg = __fdividef(1.f, 1.f + __expf(-g));
                float db = bd;
                const float* wdp = s_wdc + cc*68 + r0[ii];
                #pragma unroll
                for (int r = 0; r < 9; r++) db += rbfv[ii][r] * wdp[r];
                float t = sg * db;
                bacc[ii][0] += t*w0; bacc[ii][1] += t*w1;
                bacc[ii][2] += t*w2; bacc[ii][3] += t*w3;
            }
        }
        __syncthreads();
    }
    #pragma unroll
    for (int ii = 0; ii < 2; ii++) {
        int i = ib + ii;
        #pragma unroll
        for (int h = 0; h < 4; h++)
            g_bias[(((size_t)n*NH + h)*KK + i)*KK + j] = bacc[ii][h];
    }
}

// ---------------- kernel: attention over K neighbors, per node ----------------
__global__ __launch_bounds__(128) void k_attn()
{
    int n = blockIdx.x;
    int tid = threadIdx.x;
    int h = tid >> 5, i = tid & 31;
    __shared__ float sk[KK*CZ];
    __shared__ float sv[KK*CZ];
    for (int p = tid; p < KK*CZ; p += 128) {
        int jj = p >> 7, c = p & 127;
        size_t base = (size_t)(n*KK + jj) * 512;
        sk[p] = g_qkvo[base + 128 + c];
        sv[p] = g_qkvo[base + 256 + c];
    }
    float qr[32];
    const float scale = 0.17677669529663687f;   // 1/sqrt(32)
    size_t erow = (size_t)(n*KK + i) * 512;
    #pragma unroll
    for (int d = 0; d < 32; d++) qr[d] = g_qkvo[erow + h*32 + d] * scale;
    __syncthreads();

    float s[32];
    float mx = -1e30f;
    const float* bp = g_bias + (((size_t)n*NH + h)*KK + i)*KK;
    #pragma unroll
    for (int jj = 0; jj < 32; jj++) {
        float acc = bp[jj];
        const float* kp = sk + jj*128 + h*32;
        #pragma unroll
        for (int d = 0; d < 32; d++) acc += qr[d] * kp[d];
        s[jj] = acc;
        mx = fmaxf(mx, acc);
    }
    float sum = 0.f;
    #pragma unroll
    for (int jj = 0; jj < 32; jj++) { s[jj] = __expf(s[jj] - mx); sum += s[jj]; }
    float inv = __fdividef(1.f, sum);
    float* op = g_og + (size_t)(n*KK + i)*CZ + h*32;
    const float* ogp = g_qkvo + erow + 384 + h*32;
    #pragma unroll
    for (int d = 0; d < 32; d++) {
        float acc = 0.f;
        const float* vp = sv + h*32 + d;
        #pragma unroll
        for (int jj = 0; jj < 32; jj++) acc += s[jj] * vp[jj*128];
        op[d] = acc * inv * ogp[d];
    }
}

// ---------------- launch ----------------
extern "C" void kernel_launch(void* const* d_in, const int* in_sizes, int n_in,
                              void* d_out, int out_size)
{
    const float* nf       = (const float*)d_in[0];
    const float* trans    = (const float*)d_in[1];
    const float* ef       = (const float*)d_in[2];
    const int*   ei       = (const int*)d_in[3];      // int32 (JAX x64 disabled)
    const float* w_left   = (const float*)d_in[4];
    const float* b_left   = (const float*)d_in[5];
    const float* w_right  = (const float*)d_in[6];
    const float* b_right  = (const float*)d_in[7];
    const float* w_bgate  = (const float*)d_in[8];
    const float* b_bgate  = (const float*)d_in[9];
    const float* w_dist   = (const float*)d_in[10];
    const float* b_dist   = (const float*)d_in[11];
    const float* w_tobias = (const float*)d_in[12];
    const float* ln_g     = (const float*)d_in[13];
    const float* ln_b     = (const float*)d_in[14];
    const float* w_q      = (const float*)d_in[15];
    const float* b_q      = (const float*)d_in[16];
    const float* w_kv     = (const float*)d_in[17];
    const float* b_kv     = (const float*)d_in[18];
    const float* w_out    = (const float*)d_in[19];
    const float* b_out    = (const float*)d_in[20];
    const float* w_ogate  = (const float*)d_in[21];
    const float* b_ogate  = (const float*)d_in[22];
    float* out = (float*)d_out;

    float *p_z, *p_qkvo, *p_og, *p_wcat, *p_bcat;
    cudaGetSymbolAddress((void**)&p_z,    g_z);
    cudaGetSymbolAddress((void**)&p_qkvo, g_qkvo);
    cudaGetSymbolAddress((void**)&p_og,   g_og);
    cudaGetSymbolAddress((void**)&p_wcat, g_wcat);
    cudaGetSymbolAddress((void**)&p_bcat, g_bcat);

    k_concat<<<128, 512>>>(w_q, b_q, w_kv, b_kv, w_ogate, b_ogate);
    k_nlr<<<NN, 32>>>(nf, w_left, b_left, w_right, b_right);
    k_ln<<<EE, 128>>>(ef, ln_g, ln_b);
    {
        dim3 g(EE/128, 512/64);
        k_gemm<<<g, 256>>>(p_z, p_wcat, p_qkvo, 512, p_bcat, 384);
    }
    k_tri<<<NN, 512>>>(ei, trans, w_bgate, b_bgate, w_dist, b_dist, w_tobias);
    k_attn<<<NN, 128>>>();
    {
        dim3 g(EE/128, 128/64);
        k_gemm<<<g, 256>>>(p_og, w_out, out, 128, b_out, 1 << 30);
    }
}

// round 4
// speedup vs baseline: 1.0843x; 1.0843x over previous
#include <cuda_runtime.h>
#include <cuda_bf16.h>
#include <math.h>

#define NN   768
#define KK   32
#define CS   384
#define CZ   128
#define CG   16
#define NH   4
#define EE   (NN*KK)
#define NRBF 64

typedef unsigned long long ull;

// ---- f32x2 packed helpers (sm_100+) ----
__device__ __forceinline__ ull pk2(float lo, float hi) {
    ull r; asm("mov.b64 %0, {%1,%2};" : "=l"(r) : "f"(lo), "f"(hi)); return r;
}
__device__ __forceinline__ void upk2(ull v, float& lo, float& hi) {
    asm("mov.b64 {%0,%1}, %2;" : "=f"(lo), "=f"(hi) : "l"(v));
}
__device__ __forceinline__ ull ffma2(ull a, ull b, ull c) {
    ull d; asm("fma.rn.f32x2 %0, %1, %2, %3;" : "=l"(d) : "l"(a), "l"(b), "l"(c)); return d;
}
__device__ __forceinline__ float tanh_fast(float x) {
    float y; asm("tanh.approx.f32 %0, %1;" : "=f"(y) : "f"(x)); return y;
}

// ---------------- scratch (device globals; allocation-free) ----------------
__device__ float g_nl[NN*CG];
__device__ float g_nr[NN*CG];
__device__ float g_z[(size_t)EE*CZ];
__device__ float g_qkvo[(size_t)EE*512];        // q[0:128) k[128:256) v[256:384) sig(og)[384:512)
__device__ float g_bias[(size_t)NN*NH*KK*KK];   // [n][h][i][j]
__device__ float g_og[(size_t)EE*CZ];
__device__ float g_wcat[CZ*512];
__device__ float g_bcat[512];

// ---------------- kernel: concat projection weights ----------------
__global__ void k_concat(const float* __restrict__ wq, const float* __restrict__ bq,
                         const float* __restrict__ wkv, const float* __restrict__ bkv,
                         const float* __restrict__ wog, const float* __restrict__ bog)
{
    int c = blockIdx.x;
    int t = threadIdx.x;
    float v;
    if (t < 128)       v = wq[c*128 + t];
    else if (t < 384)  v = wkv[c*256 + (t-128)];
    else               v = wog[c*128 + (t-384)];
    g_wcat[c*512 + t] = v;
    if (c == 0) {
        float b;
        if (t < 128)      b = bq[t];
        else if (t < 384) b = bkv[t-128];
        else              b = bog[t-384];
        g_bcat[t] = b;
    }
}

// ---------------- kernel: node left/right projections ----------------
__global__ void k_nlr(const float* __restrict__ nf,
                      const float* __restrict__ wl, const float* __restrict__ bl,
                      const float* __restrict__ wr, const float* __restrict__ br)
{
    int n = blockIdx.x;
    int t = threadIdx.x;          // 32 threads
    int c0 = t & 15;
    const float* w = (t < 16) ? wl : wr;
    float acc = (t < 16) ? bl[c0] : br[c0];
    const float* row = nf + (size_t)n*CS;
    #pragma unroll 4
    for (int c = 0; c < CS; c++) acc += __ldg(row + c) * __ldg(w + c*CG + c0);
    if (t < 16) g_nl[n*CG + c0] = acc;
    else        g_nr[n*CG + c0] = acc;
}

// ---------------- kernel: LayerNorm over c_z ----------------
__global__ __launch_bounds__(128) void k_ln(const float* __restrict__ ef,
                                            const float* __restrict__ gam,
                                            const float* __restrict__ bet)
{
    int e = blockIdx.x;
    int t = threadIdx.x;
    float x = ef[(size_t)e*CZ + t];
    float s = x, s2 = x*x;
    #pragma unroll
    for (int o = 16; o > 0; o >>= 1) {
        s  += __shfl_xor_sync(0xffffffffu, s,  o);
        s2 += __shfl_xor_sync(0xffffffffu, s2, o);
    }
    __shared__ float ws[4], ws2[4];
    int w = t >> 5;
    if ((t & 31) == 0) { ws[w] = s; ws2[w] = s2; }
    __syncthreads();
    s  = ws[0]  + ws[1]  + ws[2]  + ws[3];
    s2 = ws2[0] + ws2[1] + ws2[2] + ws2[3];
    float mu  = s  * (1.f/128.f);
    float var = s2 * (1.f/128.f) - mu*mu;
    float inv = rsqrtf(var + 1e-5f);
    g_z[(size_t)e*CZ + t] = (x - mu) * inv * gam[t] + bet[t];
}

// ---------------- kernel: tiled SGEMM with f32x2  C[M,n] = A[M,128] @ B[128,n] + bias ----
// BM=128, BN=128, BK=32, 256 threads, 8x8 microtile (n packed in f32x2 pairs).
__global__ __launch_bounds__(256) void k_gemm(const float* __restrict__ A,
                                              const float* __restrict__ B,
                                              float* __restrict__ C,
                                              int ldb,
                                              const float* __restrict__ bias,
                                              int sigStart)
{
    __shared__ float As[32*132];   // [k][m]
    __shared__ float Bs[32*132];   // [k][n]
    int tid = threadIdx.x;
    int row0 = blockIdx.x * 128;
    int n0   = blockIdx.y * 128;
    int tx = tid & 15;       // 8 cols each (4 f32x2 pairs)
    int ty = tid >> 4;       // 8 rows each
    ull acc[8][4];
    #pragma unroll
    for (int m = 0; m < 8; m++)
        #pragma unroll
        for (int q = 0; q < 4; q++) acc[m][q] = 0ull;

    for (int k0 = 0; k0 < 128; k0 += 32) {
        #pragma unroll
        for (int it = 0; it < 4; it++) {
            int idx = tid + it*256;             // 0..1023
            int r = idx >> 3, kc = idx & 7;
            float4 v = *(const float4*)(A + (size_t)(row0 + r)*128 + k0 + kc*4);
            As[(kc*4+0)*132 + r] = v.x;
            As[(kc*4+1)*132 + r] = v.y;
            As[(kc*4+2)*132 + r] = v.z;
            As[(kc*4+3)*132 + r] = v.w;
        }
        #pragma unroll
        for (int it = 0; it < 4; it++) {
            int idx = tid + it*256;             // 0..1023
            int r = idx >> 5, nc = idx & 31;
            float4 v = *(const float4*)(B + (size_t)(k0 + r)*ldb + n0 + nc*4);
            *(float4*)(Bs + r*132 + nc*4) = v;
        }
        __syncthreads();
        #pragma unroll
        for (int kk = 0; kk < 32; kk++) {
            float4 a0 = *(const float4*)(As + kk*132 + ty*8);
            float4 a1 = *(const float4*)(As + kk*132 + ty*8 + 4);
            const ull* bp = (const ull*)(Bs + kk*132 + tx*8);
            ull b0 = bp[0], b1 = bp[1], b2 = bp[2], b3 = bp[3];
            float av[8] = {a0.x,a0.y,a0.z,a0.w,a1.x,a1.y,a1.z,a1.w};
            #pragma unroll
            for (int m = 0; m < 8; m++) {
                ull ad = pk2(av[m], av[m]);
                acc[m][0] = ffma2(ad, b0, acc[m][0]);
                acc[m][1] = ffma2(ad, b1, acc[m][1]);
                acc[m][2] = ffma2(ad, b2, acc[m][2]);
                acc[m][3] = ffma2(ad, b3, acc[m][3]);
            }
        }
        __syncthreads();
    }
    #pragma unroll
    for (int m = 0; m < 8; m++) {
        int row = row0 + ty*8 + m;
        #pragma unroll
        for (int q = 0; q < 4; q++) {
            int c0 = n0 + tx*8 + 2*q;
            float v0, v1;
            upk2(acc[m][q], v0, v1);
            v0 += bias[c0];
            v1 += bias[c0+1];
            if (c0   >= sigStart) v0 = __fdividef(1.f, 1.f + __expf(-v0));
            if (c0+1 >= sigStart) v1 = __fdividef(1.f, 1.f + __expf(-v1));
            float2 st = {v0, v1};
            *(float2*)(C + (size_t)row*ldb + c0) = st;
        }
    }
}

// ---------------- kernel: triangle bias ----------------
// gate[i,j,c] = sum_k e1[i,k] * M[c,j,k],  M[c,j,k] = sum_l e2[j,l] W[k*16+l,c].
// db via 8-tap even-aligned truncated RBF. bias[h,i,j] = sum_c sigm(gate)*db*wt[c,h].
// f32x2-packed contractions, tanh.approx sigmoid. Static smem ~48KB.
__global__ __launch_bounds__(512) void k_tri(const int* __restrict__ ei,
                                             const float* __restrict__ trans,
                                             const float* __restrict__ W,       // [256,128]
                                             const float* __restrict__ b_bgate,
                                             const float* __restrict__ wdist,   // [64,128]
                                             const float* __restrict__ b_dist,
                                             const float* __restrict__ wtob)    // [128,4]
{
    __shared__ float s_e2t[16*32];     // [l][j]
    __shared__ float s_t[32*4];
    __shared__ ull   s_wt2[128*4];     // [c][h] duplicated pairs             4KB
    __shared__ float s_wdc[16*64];     // [c in chunk][r]                     4KB
    __shared__ float s_M[16*32*18];    // [c in chunk][j][k], stride 18       36.9KB
    __shared__ float s_bg[128], s_bd[128];
    __shared__ int   s_src[32];

    int n = blockIdx.x;
    int tid = threadIdx.x;

    if (tid < 32) s_src[tid] = ei[n*KK + tid];
    __syncthreads();
    {
        int i = tid >> 4, k = tid & 15;
        s_e2t[k*32 + i] = g_nr[s_src[i]*CG + k];
        int c = tid >> 2, h = tid & 3;
        float w = wtob[c*4 + h];
        s_wt2[c*4 + h] = pk2(w, w);
    }
    if (tid < 96) { int i = tid/3, c = tid - i*3; s_t[i*4+c] = trans[s_src[i]*3 + c]; }
    if (tid < 128) { s_bg[tid] = b_bgate[tid]; s_bd[tid] = b_dist[tid]; }
    __syncthreads();

    // phase-B pair assignment
    int j  = tid >> 4;              // 0..31
    int ib = (tid & 15) * 2;        // i in {ib, ib+1}

    int r0[2];
    ull rbfp[2][4];                 // 8 taps packed
    ull e1p[2][8];                  // e1 row packed over k
    #pragma unroll
    for (int ii = 0; ii < 2; ii++) {
        int i = ib + ii;
        float dx = s_t[i*4+0] - s_t[j*4+0] + 1e-8f;
        float dy = s_t[i*4+1] - s_t[j*4+1] + 1e-8f;
        float dz = s_t[i*4+2] - s_t[j*4+2] + 1e-8f;
        float dd = sqrtf(dx*dx + dy*dy + dz*dz);
        int rc = (int)rintf(dd * (63.0f/20.0f));
        int rr0 = (rc - 3) & ~1;
        rr0 = max(rr0, 0); rr0 = min(rr0, 56);
        r0[ii] = rr0;
        #pragma unroll
        for (int r2 = 0; r2 < 4; r2++) {
            float mu0 = (float)(rr0 + 2*r2)     * (20.0f/63.0f);
            float mu1 = (float)(rr0 + 2*r2 + 1) * (20.0f/63.0f);
            float x0 = (dd - mu0) * 3.2f;
            float x1 = (dd - mu1) * 3.2f;
            rbfp[ii][r2] = pk2(__expf(-x0*x0), __expf(-x1*x1));
        }
        const ull* ep = (const ull*)(g_nl + s_src[i]*CG);
        #pragma unroll
        for (int k2 = 0; k2 < 8; k2++) e1p[ii][k2] = ep[k2];
    }

    // phase-A assignment
    int jA = tid & 31;              // 0..31
    int kA = tid >> 5;              // 0..15 (warp-uniform)

    ull bacc2[4] = {0ull, 0ull, 0ull, 0ull};   // packed (i0,i1) per head

    for (int ch = 0; ch < 8; ch++) {
        int cb = ch * 16;
        // stage wdist chunk: s_wdc[c][r] = wdist[r*128 + cb + c]
        #pragma unroll
        for (int it = 0; it < 2; it++) {
            int p = tid + it*512;
            int r = p >> 4, c = p & 15;
            s_wdc[c*64 + r] = __ldg(wdist + r*128 + cb + c);
        }
        // phase A (f32x2 over channel pairs)
        {
            ull a2[8];
            #pragma unroll
            for (int c2 = 0; c2 < 8; c2++) a2[c2] = 0ull;
            #pragma unroll
            for (int l = 0; l < 16; l++) {
                float e2v = s_e2t[l*32 + jA];
                ull e2p = pk2(e2v, e2v);
                const ulonglong2* Wp = (const ulonglong2*)(W + (size_t)(kA*16 + l)*128 + cb);
                ulonglong2 w01 = __ldg(Wp+0), w23 = __ldg(Wp+1), w45 = __ldg(Wp+2), w67 = __ldg(Wp+3);
                a2[0] = ffma2(e2p, w01.x, a2[0]); a2[1] = ffma2(e2p, w01.y, a2[1]);
                a2[2] = ffma2(e2p, w23.x, a2[2]); a2[3] = ffma2(e2p, w23.y, a2[3]);
                a2[4] = ffma2(e2p, w45.x, a2[4]); a2[5] = ffma2(e2p, w45.y, a2[5]);
                a2[6] = ffma2(e2p, w67.x, a2[6]); a2[7] = ffma2(e2p, w67.y, a2[7]);
            }
            #pragma unroll
            for (int c2 = 0; c2 < 8; c2++) {
                float lo, hi;
                upk2(a2[c2], lo, hi);
                s_M[((2*c2  )*32 + jA)*18 + kA] = lo;
                s_M[((2*c2+1)*32 + jA)*18 + kA] = hi;
            }
        }
        __syncthreads();
        // phase B
        #pragma unroll 1
        for (int cc = 0; cc < 16; cc++) {
            int c = cb + cc;
            const ull* mrow = (const ull*)(s_M + (cc*32 + j)*18);
            ull mk0 = mrow[0], mk1 = mrow[1], mk2_ = mrow[2], mk3 = mrow[3];
            ull mk4 = mrow[4], mk5 = mrow[5], mk6  = mrow[6], mk7 = mrow[7];
            float bg = s_bg[c], bd = s_bd[c];
            float t01[2];
            #pragma unroll
            for (int ii = 0; ii < 2; ii++) {
                ull ga = 0ull;
                ga = ffma2(e1p[ii][0], mk0,  ga);
                ga = ffma2(e1p[ii][1], mk1,  ga);
                ga = ffma2(e1p[ii][2], mk2_, ga);
                ga = ffma2(e1p[ii][3], mk3,  ga);
                ga = ffma2(e1p[ii][4], mk4,  ga);
                ga = ffma2(e1p[ii][5], mk5,  ga);
                ga = ffma2(e1p[ii][6], mk6,  ga);
                ga = ffma2(e1p[ii][7], mk7,  ga);
                float glo, ghi;
                upk2(ga, glo, ghi);
                float g = glo + ghi + bg;
                float sg = 0.5f + 0.5f*tanh_fast(0.5f*g);
                const ull* wp = (const ull*)(s_wdc + cc*64 + r0[ii]);
                ull da = 0ull;
                da = ffma2(rbfp[ii][0], wp[0], da);
                da = ffma2(rbfp[ii][1], wp[1], da);
                da = ffma2(rbfp[ii][2], wp[2], da);
                da = ffma2(rbfp[ii][3], wp[3], da);
                float dlo, dhi;
                upk2(da, dlo, dhi);
                t01[ii] = sg * (dlo + dhi + bd);
            }
            ull tp = pk2(t01[0], t01[1]);
            const ull* wt = s_wt2 + c*4;
            bacc2[0] = ffma2(tp, wt[0], bacc2[0]);
            bacc2[1] = ffma2(tp, wt[1], bacc2[1]);
            bacc2[2] = ffma2(tp, wt[2], bacc2[2]);
            bacc2[3] = ffma2(tp, wt[3], bacc2[3]);
        }
        __syncthreads();
    }
    #pragma unroll
    for (int h = 0; h < 4; h++) {
        float v0, v1;
        upk2(bacc2[h], v0, v1);
        g_bias[(((size_t)n*NH + h)*KK + ib  )*KK + j] = v0;
        g_bias[(((size_t)n*NH + h)*KK + ib+1)*KK + j] = v1;
    }
}

// ---------------- kernel: attention over K neighbors, per node ----------------
__global__ __launch_bounds__(128) void k_attn()
{
    int n = blockIdx.x;
    int tid = threadIdx.x;
    int h = tid >> 5, i = tid & 31;
    __shared__ float sk[KK*CZ];
    __shared__ float sv[KK*CZ];
    for (int p = tid; p < KK*CZ; p += 128) {
        int jj = p >> 7, c = p & 127;
        size_t base = (size_t)(n*KK + jj) * 512;
        sk[p] = g_qkvo[base + 128 + c];
        sv[p] = g_qkvo[base + 256 + c];
    }
    float qr[32];
    const float scale = 0.17677669529663687f;   // 1/sqrt(32)
    size_t erow = (size_t)(n*KK + i) * 512;
    #pragma unroll
    for (int d = 0; d < 32; d++) qr[d] = g_qkvo[erow + h*32 + d] * scale;
    __syncthreads();

    float s[32];
    float mx = -1e30f;
    const float* bp = g_bias + (((size_t)n*NH + h)*KK + i)*KK;
    #pragma unroll
    for (int jj = 0; jj < 32; jj++) {
        float acc = bp[jj];
        const float* kp = sk + jj*128 + h*32;
        #pragma unroll
        for (int d = 0; d < 32; d++) acc += qr[d] * kp[d];
        s[jj] = acc;
        mx = fmaxf(mx, acc);
    }
    float sum = 0.f;
    #pragma unroll
    for (int jj = 0; jj < 32; jj++) { s[jj] = __expf(s[jj] - mx); sum += s[jj]; }
    float inv = __fdividef(1.f, sum);
    float* op = g_og + (size_t)(n*KK + i)*CZ + h*32;
    const float* ogp = g_qkvo + erow + 384 + h*32;
    #pragma unroll
    for (int d = 0; d < 32; d++) {
        float acc = 0.f;
        const float* vp = sv + h*32 + d;
        #pragma unroll
        for (int jj = 0; jj < 32; jj++) acc += s[jj] * vp[jj*128];
        op[d] = acc * inv * ogp[d];
    }
}

// ---------------- launch ----------------
extern "C" void kernel_launch(void* const* d_in, const int* in_sizes, int n_in,
                              void* d_out, int out_size)
{
    const float* nf       = (const float*)d_in[0];
    const float* trans    = (const float*)d_in[1];
    const float* ef       = (const float*)d_in[2];
    const int*   ei       = (const int*)d_in[3];
    const float* w_left   = (const float*)d_in[4];
    const float* b_left   = (const float*)d_in[5];
    const float* w_right  = (const float*)d_in[6];
    const float* b_right  = (const float*)d_in[7];
    const float* w_bgate  = (const float*)d_in[8];
    const float* b_bgate  = (const float*)d_in[9];
    const float* w_dist   = (const float*)d_in[10];
    const float* b_dist   = (const float*)d_in[11];
    const float* w_tobias = (const float*)d_in[12];
    const float* ln_g     = (const float*)d_in[13];
    const float* ln_b     = (const float*)d_in[14];
    const float* w_q      = (const float*)d_in[15];
    const float* b_q      = (const float*)d_in[16];
    const float* w_kv     = (const float*)d_in[17];
    const float* b_kv     = (const float*)d_in[18];
    const float* w_out    = (const float*)d_in[19];
    const float* b_out    = (const float*)d_in[20];
    const float* w_ogate  = (const float*)d_in[21];
    const float* b_ogate  = (const float*)d_in[22];
    float* out = (float*)d_out;

    float *p_z, *p_qkvo, *p_og, *p_wcat, *p_bcat;
    cudaGetSymbolAddress((void**)&p_z,    g_z);
    cudaGetSymbolAddress((void**)&p_qkvo, g_qkvo);
    cudaGetSymbolAddress((void**)&p_og,   g_og);
    cudaGetSymbolAddress((void**)&p_wcat, g_wcat);
    cudaGetSymbolAddress((void**)&p_bcat, g_bcat);

    k_concat<<<128, 512>>>(w_q, b_q, w_kv, b_kv, w_ogate, b_ogate);
    k_nlr<<<NN, 32>>>(nf, w_left, b_left, w_right, b_right);
    k_ln<<<EE, 128>>>(ef, ln_g, ln_b);
    {
        dim3 g(EE/128, 512/128);
        k_gemm<<<g, 256>>>(p_z, p_wcat, p_qkvo, 512, p_bcat, 384);
    }
    k_tri<<<NN, 512>>>(ei, trans, w_bgate, b_bgate, w_dist, b_dist, w_tobias);
    k_attn<<<NN, 128>>>();
    {
        dim3 g(EE/128, 1);
        k_gemm<<<g, 256>>>(p_og, w_out, out, 128, b_out, 1 << 30);
    }
}

// round 5
// speedup vs baseline: 1.2002x; 1.1069x over previous
#include <cuda_runtime.h>
#include <cuda_bf16.h>
#include <math.h>

#define NN   768
#define KK   32
#define CS   384
#define CZ   128
#define CG   16
#define NH   4
#define EE   (NN*KK)
#define NRBF 64

typedef unsigned long long ull;
typedef unsigned int uint;

// ---- f32x2 packed helpers (sm_100+) ----
__device__ __forceinline__ ull pk2(float lo, float hi) {
    ull r; asm("mov.b64 %0, {%1,%2};" : "=l"(r) : "f"(lo), "f"(hi)); return r;
}
__device__ __forceinline__ void upk2(ull v, float& lo, float& hi) {
    asm("mov.b64 {%0,%1}, %2;" : "=f"(lo), "=f"(hi) : "l"(v));
}
__device__ __forceinline__ ull ffma2(ull a, ull b, ull c) {
    ull d; asm("fma.rn.f32x2 %0, %1, %2, %3;" : "=l"(d) : "l"(a), "l"(b), "l"(c)); return d;
}
__device__ __forceinline__ float tanh_fast(float x) {
    float y; asm("tanh.approx.f32 %0, %1;" : "=f"(y) : "f"(x)); return y;
}
// ---- tf32 helpers ----
__device__ __forceinline__ uint f2tf32(float x) {
    uint u; asm("cvt.rna.tf32.f32 %0, %1;" : "=r"(u) : "f"(x)); return u;
}
__device__ __forceinline__ void mma_tf32(float& d0, float& d1, float& d2, float& d3,
                                         uint a0, uint a1, uint a2, uint a3,
                                         uint b0, uint b1) {
    asm("mma.sync.aligned.m16n8k8.row.col.f32.tf32.tf32.f32 "
        "{%0,%1,%2,%3}, {%4,%5,%6,%7}, {%8,%9}, {%0,%1,%2,%3};"
        : "+f"(d0), "+f"(d1), "+f"(d2), "+f"(d3)
        : "r"(a0), "r"(a1), "r"(a2), "r"(a3), "r"(b0), "r"(b1));
}

// ---------------- scratch (device globals; allocation-free) ----------------
__device__ float g_nl[NN*CG];
__device__ float g_nr[NN*CG];
__device__ float g_z[(size_t)EE*CZ];
__device__ float g_qkvo[(size_t)EE*512];        // q[0:128) k[128:256) v[256:384) sig(og)[384:512)
__device__ float g_bias[(size_t)NN*NH*KK*KK];   // [n][h][i][j]
__device__ float g_og[(size_t)EE*CZ];
__device__ float g_wcat[CZ*512];
__device__ float g_bcat[512];

// ---------------- kernel: concat projection weights ----------------
__global__ void k_concat(const float* __restrict__ wq, const float* __restrict__ bq,
                         const float* __restrict__ wkv, const float* __restrict__ bkv,
                         const float* __restrict__ wog, const float* __restrict__ bog)
{
    int c = blockIdx.x;
    int t = threadIdx.x;
    float v;
    if (t < 128)       v = wq[c*128 + t];
    else if (t < 384)  v = wkv[c*256 + (t-128)];
    else               v = wog[c*128 + (t-384)];
    g_wcat[c*512 + t] = v;
    if (c == 0) {
        float b;
        if (t < 128)      b = bq[t];
        else if (t < 384) b = bkv[t-128];
        else              b = bog[t-384];
        g_bcat[t] = b;
    }
}

// ---------------- kernel: node left/right projections ----------------
__global__ void k_nlr(const float* __restrict__ nf,
                      const float* __restrict__ wl, const float* __restrict__ bl,
                      const float* __restrict__ wr, const float* __restrict__ br)
{
    int n = blockIdx.x;
    int t = threadIdx.x;          // 32 threads
    int c0 = t & 15;
    const float* w = (t < 16) ? wl : wr;
    float acc = (t < 16) ? bl[c0] : br[c0];
    const float* row = nf + (size_t)n*CS;
    #pragma unroll 4
    for (int c = 0; c < CS; c++) acc += __ldg(row + c) * __ldg(w + c*CG + c0);
    if (t < 16) g_nl[n*CG + c0] = acc;
    else        g_nr[n*CG + c0] = acc;
}

// ---------------- kernel: LayerNorm over c_z ----------------
__global__ __launch_bounds__(128) void k_ln(const float* __restrict__ ef,
                                            const float* __restrict__ gam,
                                            const float* __restrict__ bet)
{
    int e = blockIdx.x;
    int t = threadIdx.x;
    float x = ef[(size_t)e*CZ + t];
    float s = x, s2 = x*x;
    #pragma unroll
    for (int o = 16; o > 0; o >>= 1) {
        s  += __shfl_xor_sync(0xffffffffu, s,  o);
        s2 += __shfl_xor_sync(0xffffffffu, s2, o);
    }
    __shared__ float ws[4], ws2[4];
    int w = t >> 5;
    if ((t & 31) == 0) { ws[w] = s; ws2[w] = s2; }
    __syncthreads();
    s  = ws[0]  + ws[1]  + ws[2]  + ws[3];
    s2 = ws2[0] + ws2[1] + ws2[2] + ws2[3];
    float mu  = s  * (1.f/128.f);
    float var = s2 * (1.f/128.f) - mu*mu;
    float inv = rsqrtf(var + 1e-5f);
    g_z[(size_t)e*CZ + t] = (x - mu) * inv * gam[t] + bet[t];
}

// ---------------- kernel: tf32 tensor-core GEMM ----------------
// C[M, n] = A[M,128] @ B[128,n] + bias (+sigmoid for col>=sigStart)
// BM=128, BN=128, BK=32. 256 threads = 8 warps (2 m x 4 n), warp tile 64x32.
// mma.m16n8k8.tf32: per warp 4 m-tiles x 4 n-tiles.
__global__ __launch_bounds__(256) void k_gemm_tc(const float* __restrict__ A,
                                                 const float* __restrict__ B,
                                                 float* __restrict__ C,
                                                 int ldb,
                                                 const float* __restrict__ bias,
                                                 int sigStart)
{
    __shared__ uint As[32*132];   // [k][m] tf32 bits
    __shared__ uint Bs[32*132];   // [k][n] tf32 bits
    int tid = threadIdx.x;
    int row0 = blockIdx.x * 128;
    int n0   = blockIdx.y * 128;
    int wid  = tid >> 5;
    int lane = tid & 31;
    int warp_m = wid >> 2;          // 0..1
    int warp_n = wid & 3;           // 0..3
    int gid = lane >> 2;            // 0..7
    int tig = lane & 3;             // 0..3
    int m0w = warp_m * 64;
    int n0w = warp_n * 32;

    float acc[4][4][4];
    #pragma unroll
    for (int mt = 0; mt < 4; mt++)
        #pragma unroll
        for (int nt = 0; nt < 4; nt++)
            #pragma unroll
            for (int q = 0; q < 4; q++) acc[mt][nt][q] = 0.f;

    for (int k0 = 0; k0 < 128; k0 += 32) {
        #pragma unroll
        for (int it = 0; it < 4; it++) {
            int idx = tid + it*256;             // 0..1023
            int r = idx >> 3, kc = idx & 7;
            float4 v = *(const float4*)(A + (size_t)(row0 + r)*128 + k0 + kc*4);
            As[(kc*4+0)*132 + r] = f2tf32(v.x);
            As[(kc*4+1)*132 + r] = f2tf32(v.y);
            As[(kc*4+2)*132 + r] = f2tf32(v.z);
            As[(kc*4+3)*132 + r] = f2tf32(v.w);
        }
        #pragma unroll
        for (int it = 0; it < 4; it++) {
            int idx = tid + it*256;             // 0..1023
            int r = idx >> 5, nc = idx & 31;
            float4 v = *(const float4*)(B + (size_t)(k0 + r)*ldb + n0 + nc*4);
            Bs[r*132 + nc*4 + 0] = f2tf32(v.x);
            Bs[r*132 + nc*4 + 1] = f2tf32(v.y);
            Bs[r*132 + nc*4 + 2] = f2tf32(v.z);
            Bs[r*132 + nc*4 + 3] = f2tf32(v.w);
        }
        __syncthreads();
        #pragma unroll
        for (int ks = 0; ks < 4; ks++) {
            int kb = ks * 8;
            const uint* a_lo = As + (kb + tig    )*132;
            const uint* a_hi = As + (kb + tig + 4)*132;
            uint af[4][4];
            #pragma unroll
            for (int mt = 0; mt < 4; mt++) {
                int ra = m0w + mt*16 + gid;
                af[mt][0] = a_lo[ra];
                af[mt][1] = a_lo[ra + 8];
                af[mt][2] = a_hi[ra];
                af[mt][3] = a_hi[ra + 8];
            }
            const uint* b_lo = Bs + (kb + tig    )*132;
            const uint* b_hi = Bs + (kb + tig + 4)*132;
            uint bf[4][2];
            #pragma unroll
            for (int nt = 0; nt < 4; nt++) {
                int cb = n0w + nt*8 + gid;
                bf[nt][0] = b_lo[cb];
                bf[nt][1] = b_hi[cb];
            }
            #pragma unroll
            for (int mt = 0; mt < 4; mt++)
                #pragma unroll
                for (int nt = 0; nt < 4; nt++)
                    mma_tf32(acc[mt][nt][0], acc[mt][nt][1], acc[mt][nt][2], acc[mt][nt][3],
                             af[mt][0], af[mt][1], af[mt][2], af[mt][3],
                             bf[nt][0], bf[nt][1]);
        }
        __syncthreads();
    }
    // epilogue: c0,c1 -> (gid, 2tig/2tig+1); c2,c3 -> (gid+8, ...)
    #pragma unroll
    for (int mt = 0; mt < 4; mt++) {
        int rowa = row0 + m0w + mt*16 + gid;
        #pragma unroll
        for (int nt = 0; nt < 4; nt++) {
            int col = n0 + n0w + nt*8 + 2*tig;
            float b0 = __ldg(bias + col), b1 = __ldg(bias + col + 1);
            float v0 = acc[mt][nt][0] + b0;
            float v1 = acc[mt][nt][1] + b1;
            float v2 = acc[mt][nt][2] + b0;
            float v3 = acc[mt][nt][3] + b1;
            if (col   >= sigStart) { v0 = __fdividef(1.f, 1.f + __expf(-v0));
                                     v2 = __fdividef(1.f, 1.f + __expf(-v2)); }
            if (col+1 >= sigStart) { v1 = __fdividef(1.f, 1.f + __expf(-v1));
                                     v3 = __fdividef(1.f, 1.f + __expf(-v3)); }
            float2 s0 = {v0, v1};
            float2 s1 = {v2, v3};
            *(float2*)(C + (size_t)rowa*ldb + col)     = s0;
            *(float2*)(C + (size_t)(rowa+8)*ldb + col) = s1;
        }
    }
}

// ---------------- kernel: triangle bias ----------------
// gate[i,j,c] = sum_k e1[i,k] * M[c,j,k],  M[c,j,k] = sum_l e2[j,l] W[k*16+l,c].
// db via 8-tap even-aligned truncated RBF. bias[h,i,j] = sum_c sigm(gate)*db*wt[c,h].
__global__ __launch_bounds__(512) void k_tri(const int* __restrict__ ei,
                                             const float* __restrict__ trans,
                                             const float* __restrict__ W,       // [256,128]
                                             const float* __restrict__ b_bgate,
                                             const float* __restrict__ wdist,   // [64,128]
                                             const float* __restrict__ b_dist,
                                             const float* __restrict__ wtob)    // [128,4]
{
    __shared__ float s_e2t[16*32];     // [l][j]
    __shared__ float s_t[32*4];
    __shared__ ull   s_wt2[128*4];     // [c][h] duplicated pairs
    __shared__ float s_wdc[16*64];     // [c in chunk][r]
    __shared__ float s_M[16*32*18];    // [c in chunk][j][k], stride 18
    __shared__ float s_bg[128], s_bd[128];
    __shared__ int   s_src[32];

    int n = blockIdx.x;
    int tid = threadIdx.x;

    if (tid < 32) s_src[tid] = ei[n*KK + tid];
    __syncthreads();
    {
        int i = tid >> 4, k = tid & 15;
        s_e2t[k*32 + i] = g_nr[s_src[i]*CG + k];
        int c = tid >> 2, h = tid & 3;
        float w = wtob[c*4 + h];
        s_wt2[c*4 + h] = pk2(w, w);
    }
    if (tid < 96) { int i = tid/3, c = tid - i*3; s_t[i*4+c] = trans[s_src[i]*3 + c]; }
    if (tid < 128) { s_bg[tid] = b_bgate[tid]; s_bd[tid] = b_dist[tid]; }
    __syncthreads();

    int j  = tid >> 4;              // 0..31
    int ib = (tid & 15) * 2;        // i in {ib, ib+1}

    int r0[2];
    ull rbfp[2][4];
    ull e1p[2][8];
    #pragma unroll
    for (int ii = 0; ii < 2; ii++) {
        int i = ib + ii;
        float dx = s_t[i*4+0] - s_t[j*4+0] + 1e-8f;
        float dy = s_t[i*4+1] - s_t[j*4+1] + 1e-8f;
        float dz = s_t[i*4+2] - s_t[j*4+2] + 1e-8f;
        float dd = sqrtf(dx*dx + dy*dy + dz*dz);
        int rc = (int)rintf(dd * (63.0f/20.0f));
        int rr0 = (rc - 3) & ~1;
        rr0 = max(rr0, 0); rr0 = min(rr0, 56);
        r0[ii] = rr0;
        #pragma unroll
        for (int r2 = 0; r2 < 4; r2++) {
            float mu0 = (float)(rr0 + 2*r2)     * (20.0f/63.0f);
            float mu1 = (float)(rr0 + 2*r2 + 1) * (20.0f/63.0f);
            float x0 = (dd - mu0) * 3.2f;
            float x1 = (dd - mu1) * 3.2f;
            rbfp[ii][r2] = pk2(__expf(-x0*x0), __expf(-x1*x1));
        }
        const ull* ep = (const ull*)(g_nl + s_src[i]*CG);
        #pragma unroll
        for (int k2 = 0; k2 < 8; k2++) e1p[ii][k2] = ep[k2];
    }

    int jA = tid & 31;
    int kA = tid >> 5;

    ull bacc2[4] = {0ull, 0ull, 0ull, 0ull};

    for (int ch = 0; ch < 8; ch++) {
        int cb = ch * 16;
        #pragma unroll
        for (int it = 0; it < 2; it++) {
            int p = tid + it*512;
            int r = p >> 4, c = p & 15;
            s_wdc[c*64 + r] = __ldg(wdist + r*128 + cb + c);
        }
        {
            ull a2[8];
            #pragma unroll
            for (int c2 = 0; c2 < 8; c2++) a2[c2] = 0ull;
            #pragma unroll
            for (int l = 0; l < 16; l++) {
                float e2v = s_e2t[l*32 + jA];
                ull e2p = pk2(e2v, e2v);
                const ulonglong2* Wp = (const ulonglong2*)(W + (size_t)(kA*16 + l)*128 + cb);
                ulonglong2 w01 = __ldg(Wp+0), w23 = __ldg(Wp+1), w45 = __ldg(Wp+2), w67 = __ldg(Wp+3);
                a2[0] = ffma2(e2p, w01.x, a2[0]); a2[1] = ffma2(e2p, w01.y, a2[1]);
                a2[2] = ffma2(e2p, w23.x, a2[2]); a2[3] = ffma2(e2p, w23.y, a2[3]);
                a2[4] = ffma2(e2p, w45.x, a2[4]); a2[5] = ffma2(e2p, w45.y, a2[5]);
                a2[6] = ffma2(e2p, w67.x, a2[6]); a2[7] = ffma2(e2p, w67.y, a2[7]);
            }
            #pragma unroll
            for (int c2 = 0; c2 < 8; c2++) {
                float lo, hi;
                upk2(a2[c2], lo, hi);
                s_M[((2*c2  )*32 + jA)*18 + kA] = lo;
                s_M[((2*c2+1)*32 + jA)*18 + kA] = hi;
            }
        }
        __syncthreads();
        #pragma unroll 1
        for (int cc = 0; cc < 16; cc++) {
            int c = cb + cc;
            const ull* mrow = (const ull*)(s_M + (cc*32 + j)*18);
            ull mk0 = mrow[0], mk1 = mrow[1], mk2_ = mrow[2], mk3 = mrow[3];
            ull mk4 = mrow[4], mk5 = mrow[5], mk6  = mrow[6], mk7 = mrow[7];
            float bg = s_bg[c], bd = s_bd[c];
            float t01[2];
            #pragma unroll
            for (int ii = 0; ii < 2; ii++) {
                ull ga = 0ull;
                ga = ffma2(e1p[ii][0], mk0,  ga);
                ga = ffma2(e1p[ii][1], mk1,  ga);
                ga = ffma2(e1p[ii][2], mk2_, ga);
                ga = ffma2(e1p[ii][3], mk3,  ga);
                ga = ffma2(e1p[ii][4], mk4,  ga);
                ga = ffma2(e1p[ii][5], mk5,  ga);
                ga = ffma2(e1p[ii][6], mk6,  ga);
                ga = ffma2(e1p[ii][7], mk7,  ga);
                float glo, ghi;
                upk2(ga, glo, ghi);
                float g = glo + ghi + bg;
                float sg = 0.5f + 0.5f*tanh_fast(0.5f*g);
                const ull* wp = (const ull*)(s_wdc + cc*64 + r0[ii]);
                ull da = 0ull;
                da = ffma2(rbfp[ii][0], wp[0], da);
                da = ffma2(rbfp[ii][1], wp[1], da);
                da = ffma2(rbfp[ii][2], wp[2], da);
                da = ffma2(rbfp[ii][3], wp[3], da);
                float dlo, dhi;
                upk2(da, dlo, dhi);
                t01[ii] = sg * (dlo + dhi + bd);
            }
            ull tp = pk2(t01[0], t01[1]);
            const ull* wt = s_wt2 + c*4;
            bacc2[0] = ffma2(tp, wt[0], bacc2[0]);
            bacc2[1] = ffma2(tp, wt[1], bacc2[1]);
            bacc2[2] = ffma2(tp, wt[2], bacc2[2]);
            bacc2[3] = ffma2(tp, wt[3], bacc2[3]);
        }
        __syncthreads();
    }
    #pragma unroll
    for (int h = 0; h < 4; h++) {
        float v0, v1;
        upk2(bacc2[h], v0, v1);
        g_bias[(((size_t)n*NH + h)*KK + ib  )*KK + j] = v0;
        g_bias[(((size_t)n*NH + h)*KK + ib+1)*KK + j] = v1;
    }
}

// ---------------- kernel: attention over K neighbors, per node ----------------
__global__ __launch_bounds__(128) void k_attn()
{
    int n = blockIdx.x;
    int tid = threadIdx.x;
    int h = tid >> 5, i = tid & 31;
    __shared__ float sk[KK*CZ];
    __shared__ float sv[KK*CZ];
    for (int p = tid; p < KK*CZ; p += 128) {
        int jj = p >> 7, c = p & 127;
        size_t base = (size_t)(n*KK + jj) * 512;
        sk[p] = g_qkvo[base + 128 + c];
        sv[p] = g_qkvo[base + 256 + c];
    }
    float qr[32];
    const float scale = 0.17677669529663687f;   // 1/sqrt(32)
    size_t erow = (size_t)(n*KK + i) * 512;
    #pragma unroll
    for (int d = 0; d < 32; d++) qr[d] = g_qkvo[erow + h*32 + d] * scale;
    __syncthreads();

    float s[32];
    float mx = -1e30f;
    const float* bp = g_bias + (((size_t)n*NH + h)*KK + i)*KK;
    #pragma unroll
    for (int jj = 0; jj < 32; jj++) {
        float acc = bp[jj];
        const float* kp = sk + jj*128 + h*32;
        #pragma unroll
        for (int d = 0; d < 32; d++) acc += qr[d] * kp[d];
        s[jj] = acc;
        mx = fmaxf(mx, acc);
    }
    float sum = 0.f;
    #pragma unroll
    for (int jj = 0; jj < 32; jj++) { s[jj] = __expf(s[jj] - mx); sum += s[jj]; }
    float inv = __fdividef(1.f, sum);
    float* op = g_og + (size_t)(n*KK + i)*CZ + h*32;
    const float* ogp = g_qkvo + erow + 384 + h*32;
    #pragma unroll
    for (int d = 0; d < 32; d++) {
        float acc = 0.f;
        const float* vp = sv + h*32 + d;
        #pragma unroll
        for (int jj = 0; jj < 32; jj++) acc += s[jj] * vp[jj*128];
        op[d] = acc * inv * ogp[d];
    }
}

// ---------------- launch ----------------
extern "C" void kernel_launch(void* const* d_in, const int* in_sizes, int n_in,
                              void* d_out, int out_size)
{
    const float* nf       = (const float*)d_in[0];
    const float* trans    = (const float*)d_in[1];
    const float* ef       = (const float*)d_in[2];
    const int*   ei       = (const int*)d_in[3];
    const float* w_left   = (const float*)d_in[4];
    const float* b_left   = (const float*)d_in[5];
    const float* w_right  = (const float*)d_in[6];
    const float* b_right  = (const float*)d_in[7];
    const float* w_bgate  = (const float*)d_in[8];
    const float* b_bgate  = (const float*)d_in[9];
    const float* w_dist   = (const float*)d_in[10];
    const float* b_dist   = (const float*)d_in[11];
    const float* w_tobias = (const float*)d_in[12];
    const float* ln_g     = (const float*)d_in[13];
    const float* ln_b     = (const float*)d_in[14];
    const float* w_q      = (const float*)d_in[15];
    const float* b_q      = (const float*)d_in[16];
    const float* w_kv     = (const float*)d_in[17];
    const float* b_kv     = (const float*)d_in[18];
    const float* w_out    = (const float*)d_in[19];
    const float* b_out    = (const float*)d_in[20];
    const float* w_ogate  = (const float*)d_in[21];
    const float* b_ogate  = (const float*)d_in[22];
    float* out = (float*)d_out;

    float *p_z, *p_qkvo, *p_og, *p_wcat, *p_bcat;
    cudaGetSymbolAddress((void**)&p_z,    g_z);
    cudaGetSymbolAddress((void**)&p_qkvo, g_qkvo);
    cudaGetSymbolAddress((void**)&p_og,   g_og);
    cudaGetSymbolAddress((void**)&p_wcat, g_wcat);
    cudaGetSymbolAddress((void**)&p_bcat, g_bcat);

    k_concat<<<128, 512>>>(w_q, b_q, w_kv, b_kv, w_ogate, b_ogate);
    k_nlr<<<NN, 32>>>(nf, w_left, b_left, w_right, b_right);
    k_ln<<<EE, 128>>>(ef, ln_g, ln_b);
    // k_tri moved before gemm (legal: depends only on k_nlr) so ncu -s 5 -c 1
    // captures it as launch #4 next round.
    k_tri<<<NN, 512>>>(ei, trans, w_bgate, b_bgate, w_dist, b_dist, w_tobias);
    {
        dim3 g(EE/128, 512/128);
        k_gemm_tc<<<g, 256>>>(p_z, p_wcat, p_qkvo, 512, p_bcat, 384);
    }
    k_attn<<<NN, 128>>>();
    {
        dim3 g(EE/128, 1);
        k_gemm_tc<<<g, 256>>>(p_og, w_out, out, 128, b_out, 1 << 30);
    }
}

// round 7
// speedup vs baseline: 1.2673x; 1.0560x over previous
#include <cuda_runtime.h>
#include <cuda_bf16.h>
#include <math.h>

#define NN   768
#define KK   32
#define CS   384
#define CZ   128
#define CG   16
#define NH   4
#define EE   (NN*KK)
#define NRBF 64

typedef unsigned long long ull;
typedef unsigned int uint;

// ---- f32x2 packed helpers (sm_100+) ----
__device__ __forceinline__ ull pk2(float lo, float hi) {
    ull r; asm("mov.b64 %0, {%1,%2};" : "=l"(r) : "f"(lo), "f"(hi)); return r;
}
__device__ __forceinline__ void upk2(ull v, float& lo, float& hi) {
    asm("mov.b64 {%0,%1}, %2;" : "=f"(lo), "=f"(hi) : "l"(v));
}
__device__ __forceinline__ ull ffma2(ull a, ull b, ull c) {
    ull d; asm("fma.rn.f32x2 %0, %1, %2, %3;" : "=l"(d) : "l"(a), "l"(b), "l"(c)); return d;
}
__device__ __forceinline__ float tanh_fast(float x) {
    float y; asm("tanh.approx.f32 %0, %1;" : "=f"(y) : "f"(x)); return y;
}
// ---- tf32 helpers ----
__device__ __forceinline__ uint f2tf32(float x) {
    uint u; asm("cvt.rna.tf32.f32 %0, %1;" : "=r"(u) : "f"(x)); return u;
}
__device__ __forceinline__ void mma_tf32(float& d0, float& d1, float& d2, float& d3,
                                         uint a0, uint a1, uint a2, uint a3,
                                         uint b0, uint b1) {
    asm("mma.sync.aligned.m16n8k8.row.col.f32.tf32.tf32.f32 "
        "{%0,%1,%2,%3}, {%4,%5,%6,%7}, {%8,%9}, {%0,%1,%2,%3};"
        : "+f"(d0), "+f"(d1), "+f"(d2), "+f"(d3)
        : "r"(a0), "r"(a1), "r"(a2), "r"(a3), "r"(b0), "r"(b1));
}

// ---------------- scratch (device globals; allocation-free) ----------------
__device__ float g_nl[NN*CG];
__device__ float g_nr[NN*CG];
__device__ float g_z[(size_t)EE*CZ];
__device__ float g_qkvo[(size_t)EE*512];        // q[0:128) k[128:256) v[256:384) sig(og)[384:512)
__device__ float g_bias[(size_t)NN*NH*KK*KK];   // [n][h][i][j]
__device__ float g_og[(size_t)EE*CZ];
__device__ float g_wcat[CZ*512];
__device__ float g_bcat[512];

// ---------------- kernel: concat projection weights ----------------
__global__ void k_concat(const float* __restrict__ wq, const float* __restrict__ bq,
                         const float* __restrict__ wkv, const float* __restrict__ bkv,
                         const float* __restrict__ wog, const float* __restrict__ bog)
{
    int c = blockIdx.x;
    int t = threadIdx.x;
    float v;
    if (t < 128)       v = wq[c*128 + t];
    else if (t < 384)  v = wkv[c*256 + (t-128)];
    else               v = wog[c*128 + (t-384)];
    g_wcat[c*512 + t] = v;
    if (c == 0) {
        float b;
        if (t < 128)      b = bq[t];
        else if (t < 384) b = bkv[t-128];
        else              b = bog[t-384];
        g_bcat[t] = b;
    }
}

// ---------------- kernel: node left/right projections ----------------
__global__ void k_nlr(const float* __restrict__ nf,
                      const float* __restrict__ wl, const float* __restrict__ bl,
                      const float* __restrict__ wr, const float* __restrict__ br)
{
    int n = blockIdx.x;
    int t = threadIdx.x;          // 32 threads
    int c0 = t & 15;
    const float* w = (t < 16) ? wl : wr;
    float acc = (t < 16) ? bl[c0] : br[c0];
    const float* row = nf + (size_t)n*CS;
    #pragma unroll 4
    for (int c = 0; c < CS; c++) acc += __ldg(row + c) * __ldg(w + c*CG + c0);
    if (t < 16) g_nl[n*CG + c0] = acc;
    else        g_nr[n*CG + c0] = acc;
}

// ---------------- kernel: LayerNorm over c_z ----------------
__global__ __launch_bounds__(128) void k_ln(const float* __restrict__ ef,
                                            const float* __restrict__ gam,
                                            const float* __restrict__ bet)
{
    int e = blockIdx.x;
    int t = threadIdx.x;
    float x = ef[(size_t)e*CZ + t];
    float s = x, s2 = x*x;
    #pragma unroll
    for (int o = 16; o > 0; o >>= 1) {
        s  += __shfl_xor_sync(0xffffffffu, s,  o);
        s2 += __shfl_xor_sync(0xffffffffu, s2, o);
    }
    __shared__ float ws[4], ws2[4];
    int w = t >> 5;
    if ((t & 31) == 0) { ws[w] = s; ws2[w] = s2; }
    __syncthreads();
    s  = ws[0]  + ws[1]  + ws[2]  + ws[3];
    s2 = ws2[0] + ws2[1] + ws2[2] + ws2[3];
    float mu  = s  * (1.f/128.f);
    float var = s2 * (1.f/128.f) - mu*mu;
    float inv = rsqrtf(var + 1e-5f);
    g_z[(size_t)e*CZ + t] = (x - mu) * inv * gam[t] + bet[t];
}

// ---------------- kernel: tf32 tensor-core GEMM ----------------
__global__ __launch_bounds__(256) void k_gemm_tc(const float* __restrict__ A,
                                                 const float* __restrict__ B,
                                                 float* __restrict__ C,
                                                 int ldb,
                                                 const float* __restrict__ bias,
                                                 int sigStart)
{
    __shared__ uint As[32*132];   // [k][m] tf32 bits
    __shared__ uint Bs[32*132];   // [k][n] tf32 bits
    int tid = threadIdx.x;
    int row0 = blockIdx.x * 128;
    int n0   = blockIdx.y * 128;
    int wid  = tid >> 5;
    int lane = tid & 31;
    int warp_m = wid >> 2;          // 0..1
    int warp_n = wid & 3;           // 0..3
    int gid = lane >> 2;            // 0..7
    int tig = lane & 3;             // 0..3
    int m0w = warp_m * 64;
    int n0w = warp_n * 32;

    float acc[4][4][4];
    #pragma unroll
    for (int mt = 0; mt < 4; mt++)
        #pragma unroll
        for (int nt = 0; nt < 4; nt++)
            #pragma unroll
            for (int q = 0; q < 4; q++) acc[mt][nt][q] = 0.f;

    for (int k0 = 0; k0 < 128; k0 += 32) {
        #pragma unroll
        for (int it = 0; it < 4; it++) {
            int idx = tid + it*256;
            int r = idx >> 3, kc = idx & 7;
            float4 v = *(const float4*)(A + (size_t)(row0 + r)*128 + k0 + kc*4);
            As[(kc*4+0)*132 + r] = f2tf32(v.x);
            As[(kc*4+1)*132 + r] = f2tf32(v.y);
            As[(kc*4+2)*132 + r] = f2tf32(v.z);
            As[(kc*4+3)*132 + r] = f2tf32(v.w);
        }
        #pragma unroll
        for (int it = 0; it < 4; it++) {
            int idx = tid + it*256;
            int r = idx >> 5, nc = idx & 31;
            float4 v = *(const float4*)(B + (size_t)(k0 + r)*ldb + n0 + nc*4);
            Bs[r*132 + nc*4 + 0] = f2tf32(v.x);
            Bs[r*132 + nc*4 + 1] = f2tf32(v.y);
            Bs[r*132 + nc*4 + 2] = f2tf32(v.z);
            Bs[r*132 + nc*4 + 3] = f2tf32(v.w);
        }
        __syncthreads();
        #pragma unroll
        for (int ks = 0; ks < 4; ks++) {
            int kb = ks * 8;
            const uint* a_lo = As + (kb + tig    )*132;
            const uint* a_hi = As + (kb + tig + 4)*132;
            uint af[4][4];
            #pragma unroll
            for (int mt = 0; mt < 4; mt++) {
                int ra = m0w + mt*16 + gid;
                af[mt][0] = a_lo[ra];
                af[mt][1] = a_lo[ra + 8];
                af[mt][2] = a_hi[ra];
                af[mt][3] = a_hi[ra + 8];
            }
            const uint* b_lo = Bs + (kb + tig    )*132;
            const uint* b_hi = Bs + (kb + tig + 4)*132;
            uint bf[4][2];
            #pragma unroll
            for (int nt = 0; nt < 4; nt++) {
                int cb = n0w + nt*8 + gid;
                bf[nt][0] = b_lo[cb];
                bf[nt][1] = b_hi[cb];
            }
            #pragma unroll
            for (int mt = 0; mt < 4; mt++)
                #pragma unroll
                for (int nt = 0; nt < 4; nt++)
                    mma_tf32(acc[mt][nt][0], acc[mt][nt][1], acc[mt][nt][2], acc[mt][nt][3],
                             af[mt][0], af[mt][1], af[mt][2], af[mt][3],
                             bf[nt][0], bf[nt][1]);
        }
        __syncthreads();
    }
    #pragma unroll
    for (int mt = 0; mt < 4; mt++) {
        int rowa = row0 + m0w + mt*16 + gid;
        #pragma unroll
        for (int nt = 0; nt < 4; nt++) {
            int col = n0 + n0w + nt*8 + 2*tig;
            float b0 = __ldg(bias + col), b1 = __ldg(bias + col + 1);
            float v0 = acc[mt][nt][0] + b0;
            float v1 = acc[mt][nt][1] + b1;
            float v2 = acc[mt][nt][2] + b0;
            float v3 = acc[mt][nt][3] + b1;
            if (col   >= sigStart) { v0 = __fdividef(1.f, 1.f + __expf(-v0));
                                     v2 = __fdividef(1.f, 1.f + __expf(-v2)); }
            if (col+1 >= sigStart) { v1 = __fdividef(1.f, 1.f + __expf(-v1));
                                     v3 = __fdividef(1.f, 1.f + __expf(-v3)); }
            float2 s0 = {v0, v1};
            float2 s1 = {v2, v3};
            *(float2*)(C + (size_t)rowa*ldb + col)     = s0;
            *(float2*)(C + (size_t)(rowa+8)*ldb + col) = s1;
        }
    }
}

// ---------------- kernel: triangle bias ----------------
// gate[i,j,c] = sum_k e1[i,k] * M[c,j,k],  M[c,j,k] = sum_l e2[j,l] W[k*16+l,c].
// db via 8-tap 16B-ALIGNED truncated RBF window (2x LDS.128 instead of 4x
// scattered LDS.64 — kills the smem-crossbar conflicts ncu showed).
// bias[h,i,j] = sum_c sigm(gate)*db*wt[c,h].
__global__ __launch_bounds__(512) void k_tri(const int* __restrict__ ei,
                                             const float* __restrict__ trans,
                                             const float* __restrict__ W,       // [256,128]
                                             const float* __restrict__ b_bgate,
                                             const float* __restrict__ wdist,   // [64,128]
                                             const float* __restrict__ b_dist,
                                             const float* __restrict__ wtob)    // [128,4]
{
    __shared__ float s_e2t[16*32];     // [l][j]                              2KB
    __shared__ float s_t[32*4];
    __shared__ ull   s_wt2[128*2];     // [c][h-pair]: (h0,h1),(h2,h3)        2KB
    __shared__ float s_wdc[16*68];     // [c in chunk][r], 16B-aligned rows   4.25KB
    __shared__ float s_M[16*32*18];    // [c in chunk][j][k], stride 18       36.9KB
    __shared__ ull   s_bgd[128];       // pk2(b_bgate, b_dist)                1KB
    __shared__ int   s_src[32];

    int n = blockIdx.x;
    int tid = threadIdx.x;

    if (tid < 32) s_src[tid] = ei[n*KK + tid];
    __syncthreads();
    {
        int i = tid >> 4, k = tid & 15;
        s_e2t[k*32 + i] = g_nr[s_src[i]*CG + k];
    }
    if (tid < 256) {
        int c = tid >> 1, p = tid & 1;
        s_wt2[c*2 + p] = pk2(wtob[c*4 + 2*p], wtob[c*4 + 2*p + 1]);
    }
    if (tid < 96) { int i = tid/3, c = tid - i*3; s_t[i*4+c] = trans[s_src[i]*3 + c]; }
    if (tid < 128) s_bgd[tid] = pk2(b_bgate[tid], b_dist[tid]);
    __syncthreads();

    int j  = tid >> 4;              // 0..31
    int ib = (tid & 15) * 2;        // i in {ib, ib+1}

    int r0[2];
    ull rbfp[2][4];                 // 8 taps, pair-packed
    ull e1p[2][8];                  // e1 row packed over k
    #pragma unroll
    for (int ii = 0; ii < 2; ii++) {
        int i = ib + ii;
        float dx = s_t[i*4+0] - s_t[j*4+0] + 1e-8f;
        float dy = s_t[i*4+1] - s_t[j*4+1] + 1e-8f;
        float dz = s_t[i*4+2] - s_t[j*4+2] + 1e-8f;
        float dd = sqrtf(dx*dx + dy*dy + dz*dz);
        float du = dd * (63.0f/20.0f);
        int f = (int)du;                 // floor (du >= 0)
        int rr0 = (f - 2) & ~3;          // 16B-aligned window base
        rr0 = max(rr0, 0); rr0 = min(rr0, 56);
        r0[ii] = rr0;
        // window [rr0, rr0+7] always covers [f-2, f+3] => dropped taps are
        // >= 2 grid units (2.03 sigma) away: weight <= e^-4.13 = 0.016 of db.
        #pragma unroll
        for (int r2 = 0; r2 < 4; r2++) {
            float mu0 = (float)(rr0 + 2*r2)     * (20.0f/63.0f);
            float mu1 = (float)(rr0 + 2*r2 + 1) * (20.0f/63.0f);
            float x0 = (dd - mu0) * 3.2f;
            float x1 = (dd - mu1) * 3.2f;
            rbfp[ii][r2] = pk2(__expf(-x0*x0), __expf(-x1*x1));
        }
        const ull* ep = (const ull*)(g_nl + s_src[i]*CG);
        #pragma unroll
        for (int k2 = 0; k2 < 8; k2++) e1p[ii][k2] = ep[k2];
    }

    int jA = tid & 31;
    int kA = tid >> 5;

    ull bacc[2][2] = {{0ull, 0ull}, {0ull, 0ull}};   // [ii][h-pair]

    for (int ch = 0; ch < 8; ch++) {
        int cb = ch * 16;
        #pragma unroll
        for (int it = 0; it < 2; it++) {
            int p = tid + it*512;
            int r = p >> 4, c = p & 15;
            s_wdc[c*68 + r] = __ldg(wdist + r*128 + cb + c);
        }
        // phase A: M[c][j][k] = sum_l e2[j,l] * W[(k*16+l)*128 + cb+c]
        {
            ull a2[8];
            #pragma unroll
            for (int c2 = 0; c2 < 8; c2++) a2[c2] = 0ull;
            #pragma unroll
            for (int l = 0; l < 16; l++) {
                float e2v = s_e2t[l*32 + jA];
                ull e2p = pk2(e2v, e2v);
                const ulonglong2* Wp = (const ulonglong2*)(W + (size_t)(kA*16 + l)*128 + cb);
                ulonglong2 w01 = __ldg(Wp+0), w23 = __ldg(Wp+1), w45 = __ldg(Wp+2), w67 = __ldg(Wp+3);
                a2[0] = ffma2(e2p, w01.x, a2[0]); a2[1] = ffma2(e2p, w01.y, a2[1]);
                a2[2] = ffma2(e2p, w23.x, a2[2]); a2[3] = ffma2(e2p, w23.y, a2[3]);
                a2[4] = ffma2(e2p, w45.x, a2[4]); a2[5] = ffma2(e2p, w45.y, a2[5]);
                a2[6] = ffma2(e2p, w67.x, a2[6]); a2[7] = ffma2(e2p, w67.y, a2[7]);
            }
            #pragma unroll
            for (int c2 = 0; c2 < 8; c2++) {
                float lo, hi;
                upk2(a2[c2], lo, hi);
                s_M[((2*c2  )*32 + jA)*18 + kA] = lo;
                s_M[((2*c2+1)*32 + jA)*18 + kA] = hi;
            }
        }
        __syncthreads();
        // phase B
        #pragma unroll 1
        for (int cc = 0; cc < 16; cc++) {
            int c = cb + cc;
            const ull* mrow = (const ull*)(s_M + (cc*32 + j)*18);
            ull mk0 = mrow[0], mk1 = mrow[1], mk2_ = mrow[2], mk3 = mrow[3];
            ull mk4 = mrow[4], mk5 = mrow[5], mk6  = mrow[6], mk7 = mrow[7];
            float bg, bd;
            upk2(s_bgd[c], bg, bd);
            float t01[2];
            #pragma unroll
            for (int ii = 0; ii < 2; ii++) {
                ull ga = 0ull;
                ga = ffma2(e1p[ii][0], mk0,  ga);
                ga = ffma2(e1p[ii][1], mk1,  ga);
                ga = ffma2(e1p[ii][2], mk2_, ga);
                ga = ffma2(e1p[ii][3], mk3,  ga);
                ga = ffma2(e1p[ii][4], mk4,  ga);
                ga = ffma2(e1p[ii][5], mk5,  ga);
                ga = ffma2(e1p[ii][6], mk6,  ga);
                ga = ffma2(e1p[ii][7], mk7,  ga);
                float glo, ghi;
                upk2(ga, glo, ghi);
                float g = glo + ghi + bg;
                float sg = 0.5f + 0.5f*tanh_fast(0.5f*g);
                // 16B-aligned 8-tap window: two LDS.128
                const ulonglong2* wp = (const ulonglong2*)(s_wdc + cc*68 + r0[ii]);
                ulonglong2 wv0 = wp[0];
                ulonglong2 wv1 = wp[1];
                ull da = 0ull;
                da = ffma2(rbfp[ii][0], wv0.x, da);
                da = ffma2(rbfp[ii][1], wv0.y, da);
                da = ffma2(rbfp[ii][2], wv1.x, da);
                da = ffma2(rbfp[ii][3], wv1.y, da);
                float dlo, dhi;
                upk2(da, dlo, dhi);
                t01[ii] = sg * (dlo + dhi + bd);
            }
            const ull* wt = s_wt2 + c*2;
            ull wt0 = wt[0], wt1 = wt[1];
            ull tp0 = pk2(t01[0], t01[0]);
            ull tp1 = pk2(t01[1], t01[1]);
            bacc[0][0] = ffma2(tp0, wt0, bacc[0][0]);
            bacc[0][1] = ffma2(tp0, wt1, bacc[0][1]);
            bacc[1][0] = ffma2(tp1, wt0, bacc[1][0]);
            bacc[1][1] = ffma2(tp1, wt1, bacc[1][1]);
        }
        __syncthreads();
    }
    #pragma unroll
    for (int ii = 0; ii < 2; ii++) {
        int i = ib + ii;
        float b0, b1, b2, b3;
        upk2(bacc[ii][0], b0, b1);
        upk2(bacc[ii][1], b2, b3);
        g_bias[(((size_t)n*NH + 0)*KK + i)*KK + j] = b0;
        g_bias[(((size_t)n*NH + 1)*KK + i)*KK + j] = b1;
        g_bias[(((size_t)n*NH + 2)*KK + i)*KK + j] = b2;
        g_bias[(((size_t)n*NH + 3)*KK + i)*KK + j] = b3;
    }
}

// ---------------- kernel: attention over K neighbors, per node ----------------
__global__ __launch_bounds__(128) void k_attn()
{
    int n = blockIdx.x;
    int tid = threadIdx.x;
    int h = tid >> 5, i = tid & 31;
    __shared__ float sk[KK*CZ];
    __shared__ float sv[KK*CZ];
    for (int p = tid; p < KK*CZ; p += 128) {
        int jj = p >> 7, c = p & 127;
        size_t base = (size_t)(n*KK + jj) * 512;
        sk[p] = g_qkvo[base + 128 + c];
        sv[p] = g_qkvo[base + 256 + c];
    }
    float qr[32];
    const float scale = 0.17677669529663687f;   // 1/sqrt(32)
    size_t erow = (size_t)(n*KK + i) * 512;
    #pragma unroll
    for (int d = 0; d < 32; d++) qr[d] = g_qkvo[erow + h*32 + d] * scale;
    __syncthreads();

    float s[32];
    float mx = -1e30f;
    const float* bp = g_bias + (((size_t)n*NH + h)*KK + i)*KK;
    #pragma unroll
    for (int jj = 0; jj < 32; jj++) {
        float acc = bp[jj];
        const float* kp = sk + jj*128 + h*32;
        #pragma unroll
        for (int d = 0; d < 32; d++) acc += qr[d] * kp[d];
        s[jj] = acc;
        mx = fmaxf(mx, acc);
    }
    float sum = 0.f;
    #pragma unroll
    for (int jj = 0; jj < 32; jj++) { s[jj] = __expf(s[jj] - mx); sum += s[jj]; }
    float inv = __fdividef(1.f, sum);
    float* op = g_og + (size_t)(n*KK + i)*CZ + h*32;
    const float* ogp = g_qkvo + erow + 384 + h*32;
    #pragma unroll
    for (int d = 0; d < 32; d++) {
        float acc = 0.f;
        const float* vp = sv + h*32 + d;
        #pragma unroll
        for (int jj = 0; jj < 32; jj++) acc += s[jj] * vp[jj*128];
        op[d] = acc * inv * ogp[d];
    }
}

// ---------------- launch ----------------
extern "C" void kernel_launch(void* const* d_in, const int* in_sizes, int n_in,
                              void* d_out, int out_size)
{
    const float* nf       = (const float*)d_in[0];
    const float* trans    = (const float*)d_in[1];
    const float* ef       = (const float*)d_in[2];
    const int*   ei       = (const int*)d_in[3];
    const float* w_left   = (const float*)d_in[4];
    const float* b_left   = (const float*)d_in[5];
    const float* w_right  = (const float*)d_in[6];
    const float* b_right  = (const float*)d_in[7];
    const float* w_bgate  = (const float*)d_in[8];
    const float* b_bgate  = (const float*)d_in[9];
    const float* w_dist   = (const float*)d_in[10];
    const float* b_dist   = (const float*)d_in[11];
    const float* w_tobias = (const float*)d_in[12];
    const float* ln_g     = (const float*)d_in[13];
    const float* ln_b     = (const float*)d_in[14];
    const float* w_q      = (const float*)d_in[15];
    const float* b_q      = (const float*)d_in[16];
    const float* w_kv     = (const float*)d_in[17];
    const float* b_kv     = (const float*)d_in[18];
    const float* w_out    = (const float*)d_in[19];
    const float* b_out    = (const float*)d_in[20];
    const float* w_ogate  = (const float*)d_in[21];
    const float* b_ogate  = (const float*)d_in[22];
    float* out = (float*)d_out;

    float *p_z, *p_qkvo, *p_og, *p_wcat, *p_bcat;
    cudaGetSymbolAddress((void**)&p_z,    g_z);
    cudaGetSymbolAddress((void**)&p_qkvo, g_qkvo);
    cudaGetSymbolAddress((void**)&p_og,   g_og);
    cudaGetSymbolAddress((void**)&p_wcat, g_wcat);
    cudaGetSymbolAddress((void**)&p_bcat, g_bcat);

    k_concat<<<128, 512>>>(w_q, b_q, w_kv, b_kv, w_ogate, b_ogate);
    k_nlr<<<NN, 32>>>(nf, w_left, b_left, w_right, b_right);
    k_ln<<<EE, 128>>>(ef, ln_g, ln_b);
    // k_tri is launch #4 (ncu -s 5 -c 1 captures it)
    k_tri<<<NN, 512>>>(ei, trans, w_bgate, b_bgate, w_dist, b_dist, w_tobias);
    {
        dim3 g(EE/128, 512/128);
        k_gemm_tc<<<g, 256>>>(p_z, p_wcat, p_qkvo, 512, p_bcat, 384);
    }
    k_attn<<<NN, 128>>>();
    {
        dim3 g(EE/128, 1);
        k_gemm_tc<<<g, 256>>>(p_og, w_out, out, 128, b_out, 1 << 30);
    }
}

// round 8
// speedup vs baseline: 1.3043x; 1.0292x over previous
#include <cuda_runtime.h>
#include <cuda_bf16.h>
#include <math.h>

#define NN   768
#define KK   32
#define CS   384
#define CZ   128
#define CG   16
#define NH   4
#define EE   (NN*KK)
#define NRBF 64

typedef unsigned long long ull;
typedef unsigned int uint;

// ---- f32x2 packed helpers (sm_100+) ----
__device__ __forceinline__ ull pk2(float lo, float hi) {
    ull r; asm("mov.b64 %0, {%1,%2};" : "=l"(r) : "f"(lo), "f"(hi)); return r;
}
__device__ __forceinline__ void upk2(ull v, float& lo, float& hi) {
    asm("mov.b64 {%0,%1}, %2;" : "=f"(lo), "=f"(hi) : "l"(v));
}
__device__ __forceinline__ ull ffma2(ull a, ull b, ull c) {
    ull d; asm("fma.rn.f32x2 %0, %1, %2, %3;" : "=l"(d) : "l"(a), "l"(b), "l"(c)); return d;
}
__device__ __forceinline__ float tanh_fast(float x) {
    float y; asm("tanh.approx.f32 %0, %1;" : "=f"(y) : "f"(x)); return y;
}
__device__ __forceinline__ __nv_bfloat162 u2b(uint u) {
    return *reinterpret_cast<__nv_bfloat162*>(&u);
}
// ---- tf32 helpers ----
__device__ __forceinline__ uint f2tf32(float x) {
    uint u; asm("cvt.rna.tf32.f32 %0, %1;" : "=r"(u) : "f"(x)); return u;
}
__device__ __forceinline__ void mma_tf32(float& d0, float& d1, float& d2, float& d3,
                                         uint a0, uint a1, uint a2, uint a3,
                                         uint b0, uint b1) {
    asm("mma.sync.aligned.m16n8k8.row.col.f32.tf32.tf32.f32 "
        "{%0,%1,%2,%3}, {%4,%5,%6,%7}, {%8,%9}, {%0,%1,%2,%3};"
        : "+f"(d0), "+f"(d1), "+f"(d2), "+f"(d3)
        : "r"(a0), "r"(a1), "r"(a2), "r"(a3), "r"(b0), "r"(b1));
}

// ---------------- scratch (device globals; allocation-free) ----------------
__device__ float g_nl[NN*CG];
__device__ float g_nr[NN*CG];
__device__ float g_z[(size_t)EE*CZ];
__device__ float g_qkvo[(size_t)EE*512];        // q[0:128) k[128:256) v[256:384) sig(og)[384:512)
__device__ float g_bias[(size_t)NN*NH*KK*KK];   // [n][h][i][j]
__device__ float g_og[(size_t)EE*CZ];
__device__ float g_wcat[CZ*512];
__device__ float g_bcat[512];

// ---------------- kernel: concat projection weights ----------------
__global__ void k_concat(const float* __restrict__ wq, const float* __restrict__ bq,
                         const float* __restrict__ wkv, const float* __restrict__ bkv,
                         const float* __restrict__ wog, const float* __restrict__ bog)
{
    int c = blockIdx.x;
    int t = threadIdx.x;
    float v;
    if (t < 128)       v = wq[c*128 + t];
    else if (t < 384)  v = wkv[c*256 + (t-128)];
    else               v = wog[c*128 + (t-384)];
    g_wcat[c*512 + t] = v;
    if (c == 0) {
        float b;
        if (t < 128)      b = bq[t];
        else if (t < 384) b = bkv[t-128];
        else              b = bog[t-384];
        g_bcat[t] = b;
    }
}

// ---------------- kernel: node left/right projections ----------------
__global__ void k_nlr(const float* __restrict__ nf,
                      const float* __restrict__ wl, const float* __restrict__ bl,
                      const float* __restrict__ wr, const float* __restrict__ br)
{
    int n = blockIdx.x;
    int t = threadIdx.x;          // 32 threads
    int c0 = t & 15;
    const float* w = (t < 16) ? wl : wr;
    float acc = (t < 16) ? bl[c0] : br[c0];
    const float* row = nf + (size_t)n*CS;
    #pragma unroll 4
    for (int c = 0; c < CS; c++) acc += __ldg(row + c) * __ldg(w + c*CG + c0);
    if (t < 16) g_nl[n*CG + c0] = acc;
    else        g_nr[n*CG + c0] = acc;
}

// ---------------- kernel: LayerNorm over c_z ----------------
__global__ __launch_bounds__(128) void k_ln(const float* __restrict__ ef,
                                            const float* __restrict__ gam,
                                            const float* __restrict__ bet)
{
    int e = blockIdx.x;
    int t = threadIdx.x;
    float x = ef[(size_t)e*CZ + t];
    float s = x, s2 = x*x;
    #pragma unroll
    for (int o = 16; o > 0; o >>= 1) {
        s  += __shfl_xor_sync(0xffffffffu, s,  o);
        s2 += __shfl_xor_sync(0xffffffffu, s2, o);
    }
    __shared__ float ws[4], ws2[4];
    int w = t >> 5;
    if ((t & 31) == 0) { ws[w] = s; ws2[w] = s2; }
    __syncthreads();
    s  = ws[0]  + ws[1]  + ws[2]  + ws[3];
    s2 = ws2[0] + ws2[1] + ws2[2] + ws2[3];
    float mu  = s  * (1.f/128.f);
    float var = s2 * (1.f/128.f) - mu*mu;
    float inv = rsqrtf(var + 1e-5f);
    g_z[(size_t)e*CZ + t] = (x - mu) * inv * gam[t] + bet[t];
}

// ---------------- kernel: tf32 tensor-core GEMM ----------------
__global__ __launch_bounds__(256) void k_gemm_tc(const float* __restrict__ A,
                                                 const float* __restrict__ B,
                                                 float* __restrict__ C,
                                                 int ldb,
                                                 const float* __restrict__ bias,
                                                 int sigStart)
{
    __shared__ uint As[32*132];   // [k][m] tf32 bits
    __shared__ uint Bs[32*132];   // [k][n] tf32 bits
    int tid = threadIdx.x;
    int row0 = blockIdx.x * 128;
    int n0   = blockIdx.y * 128;
    int wid  = tid >> 5;
    int lane = tid & 31;
    int warp_m = wid >> 2;          // 0..1
    int warp_n = wid & 3;           // 0..3
    int gid = lane >> 2;            // 0..7
    int tig = lane & 3;             // 0..3
    int m0w = warp_m * 64;
    int n0w = warp_n * 32;

    float acc[4][4][4];
    #pragma unroll
    for (int mt = 0; mt < 4; mt++)
        #pragma unroll
        for (int nt = 0; nt < 4; nt++)
            #pragma unroll
            for (int q = 0; q < 4; q++) acc[mt][nt][q] = 0.f;

    for (int k0 = 0; k0 < 128; k0 += 32) {
        #pragma unroll
        for (int it = 0; it < 4; it++) {
            int idx = tid + it*256;
            int r = idx >> 3, kc = idx & 7;
            float4 v = *(const float4*)(A + (size_t)(row0 + r)*128 + k0 + kc*4);
            As[(kc*4+0)*132 + r] = f2tf32(v.x);
            As[(kc*4+1)*132 + r] = f2tf32(v.y);
            As[(kc*4+2)*132 + r] = f2tf32(v.z);
            As[(kc*4+3)*132 + r] = f2tf32(v.w);
        }
        #pragma unroll
        for (int it = 0; it < 4; it++) {
            int idx = tid + it*256;
            int r = idx >> 5, nc = idx & 31;
            float4 v = *(const float4*)(B + (size_t)(k0 + r)*ldb + n0 + nc*4);
            Bs[r*132 + nc*4 + 0] = f2tf32(v.x);
            Bs[r*132 + nc*4 + 1] = f2tf32(v.y);
            Bs[r*132 + nc*4 + 2] = f2tf32(v.z);
            Bs[r*132 + nc*4 + 3] = f2tf32(v.w);
        }
        __syncthreads();
        #pragma unroll
        for (int ks = 0; ks < 4; ks++) {
            int kb = ks * 8;
            const uint* a_lo = As + (kb + tig    )*132;
            const uint* a_hi = As + (kb + tig + 4)*132;
            uint af[4][4];
            #pragma unroll
            for (int mt = 0; mt < 4; mt++) {
                int ra = m0w + mt*16 + gid;
                af[mt][0] = a_lo[ra];
                af[mt][1] = a_lo[ra + 8];
                af[mt][2] = a_hi[ra];
                af[mt][3] = a_hi[ra + 8];
            }
            const uint* b_lo = Bs + (kb + tig    )*132;
            const uint* b_hi = Bs + (kb + tig + 4)*132;
            uint bf[4][2];
            #pragma unroll
            for (int nt = 0; nt < 4; nt++) {
                int cb = n0w + nt*8 + gid;
                bf[nt][0] = b_lo[cb];
                bf[nt][1] = b_hi[cb];
            }
            #pragma unroll
            for (int mt = 0; mt < 4; mt++)
                #pragma unroll
                for (int nt = 0; nt < 4; nt++)
                    mma_tf32(acc[mt][nt][0], acc[mt][nt][1], acc[mt][nt][2], acc[mt][nt][3],
                             af[mt][0], af[mt][1], af[mt][2], af[mt][3],
                             bf[nt][0], bf[nt][1]);
        }
        __syncthreads();
    }
    #pragma unroll
    for (int mt = 0; mt < 4; mt++) {
        int rowa = row0 + m0w + mt*16 + gid;
        #pragma unroll
        for (int nt = 0; nt < 4; nt++) {
            int col = n0 + n0w + nt*8 + 2*tig;
            float b0 = __ldg(bias + col), b1 = __ldg(bias + col + 1);
            float v0 = acc[mt][nt][0] + b0;
            float v1 = acc[mt][nt][1] + b1;
            float v2 = acc[mt][nt][2] + b0;
            float v3 = acc[mt][nt][3] + b1;
            if (col   >= sigStart) { v0 = __fdividef(1.f, 1.f + __expf(-v0));
                                     v2 = __fdividef(1.f, 1.f + __expf(-v2)); }
            if (col+1 >= sigStart) { v1 = __fdividef(1.f, 1.f + __expf(-v1));
                                     v3 = __fdividef(1.f, 1.f + __expf(-v3)); }
            float2 s0 = {v0, v1};
            float2 s1 = {v2, v3};
            *(float2*)(C + (size_t)rowa*ldb + col)     = s0;
            *(float2*)(C + (size_t)(rowa+8)*ldb + col) = s1;
        }
    }
}

// ---------------- kernel: triangle bias ----------------
// gate[i,j,c] = sum_k e1[i,k] * M[c,j,k],  M[c,j,k] = sum_l e2[j,l] W[k*16+l,c].
// Inner contractions in bf16 (HFMA2) with bf16 smem tiles: halves the smem
// bytes, which is the binding resource (L1 crossbar at 78% in ncu).
// db via 16-tap 8-aligned bf16 window: 2x LDS.128, all lanes within <=7
// distinct 16B lines -> ~1 wavefront each.
__global__ __launch_bounds__(512) void k_tri(const int* __restrict__ ei,
                                             const float* __restrict__ trans,
                                             const float* __restrict__ W,       // [256,128]
                                             const float* __restrict__ b_bgate,
                                             const float* __restrict__ wdist,   // [64,128]
                                             const float* __restrict__ b_dist,
                                             const float* __restrict__ wtob)    // [128,4]
{
    __shared__ float          s_e2t[16*32];     // [l][j]                   2048B
    __shared__ float          s_t[32*4];        //                           512B
    __shared__ ull            s_wt2[128*2];     // [c][h-pair]              2048B
    __shared__ __nv_bfloat16  s_wdc[16*72];     // [c in chunk][r] bf16     2304B
    __shared__ __nv_bfloat16  s_M[16*32*40];    // [c][j][k] bf16, str 40  40960B
    __shared__ ull            s_bgd[128];       // pk2(bg, bd)              1024B
    __shared__ int            s_src[32];        //                           128B

    int n = blockIdx.x;
    int tid = threadIdx.x;

    if (tid < 32) s_src[tid] = ei[n*KK + tid];
    __syncthreads();
    {
        int i = tid >> 4, k = tid & 15;
        s_e2t[k*32 + i] = g_nr[s_src[i]*CG + k];
    }
    if (tid < 256) {
        int c = tid >> 1, p = tid & 1;
        s_wt2[c*2 + p] = pk2(wtob[c*4 + 2*p], wtob[c*4 + 2*p + 1]);
    }
    if (tid < 96) { int i = tid/3, c = tid - i*3; s_t[i*4+c] = trans[s_src[i]*3 + c]; }
    if (tid < 128) s_bgd[tid] = pk2(b_bgate[tid], b_dist[tid]);
    __syncthreads();

    int j  = tid >> 4;              // 0..31
    int ib = (tid & 15) * 2;        // i in {ib, ib+1}

    int r0[2];
    __nv_bfloat162 rbfh[2][8];      // 16 taps, pair-packed bf16
    __nv_bfloat162 e1h[2][8];       // e1 row pair-packed bf16
    #pragma unroll
    for (int ii = 0; ii < 2; ii++) {
        int i = ib + ii;
        float dx = s_t[i*4+0] - s_t[j*4+0] + 1e-8f;
        float dy = s_t[i*4+1] - s_t[j*4+1] + 1e-8f;
        float dz = s_t[i*4+2] - s_t[j*4+2] + 1e-8f;
        float dd = sqrtf(dx*dx + dy*dy + dz*dz);
        int f = (int)(dd * (63.0f/20.0f));
        int rr0 = (f - 4) & ~7;          // 16B(bf16)-aligned 16-tap window
        rr0 = max(rr0, 0); rr0 = min(rr0, 48);
        r0[ii] = rr0;
        // window [rr0, rr0+15] covers [f-4, f+4]; dropped taps >= 4 grid
        // units (4.06 sigma): weight <= e^-16.5.
        #pragma unroll
        for (int r2 = 0; r2 < 8; r2++) {
            float mu0 = (float)(rr0 + 2*r2)     * (20.0f/63.0f);
            float mu1 = (float)(rr0 + 2*r2 + 1) * (20.0f/63.0f);
            float x0 = (dd - mu0) * 3.2f;
            float x1 = (dd - mu1) * 3.2f;
            rbfh[ii][r2] = __floats2bfloat162_rn(__expf(-x0*x0), __expf(-x1*x1));
        }
        const float4* ep = (const float4*)(g_nl + s_src[i]*CG);
        #pragma unroll
        for (int q = 0; q < 4; q++) {
            float4 e4 = __ldg(ep + q);
            e1h[ii][2*q  ] = __floats2bfloat162_rn(e4.x, e4.y);
            e1h[ii][2*q+1] = __floats2bfloat162_rn(e4.z, e4.w);
        }
    }

    int jA = tid & 31;
    int kA = tid >> 5;

    ull bacc[2][2] = {{0ull, 0ull}, {0ull, 0ull}};   // [ii][h-pair], f32x2

    for (int ch = 0; ch < 8; ch++) {
        int cb = ch * 16;
        // stage wdist chunk as bf16: s_wdc[c][r], rows padded to 72
        {
            int c = tid & 15, rp = tid >> 4;     // rp 0..31 -> r = 2rp
            float v0 = __ldg(wdist + (2*rp  )*128 + cb + c);
            float v1 = __ldg(wdist + (2*rp+1)*128 + cb + c);
            *(__nv_bfloat162*)(s_wdc + c*72 + 2*rp) = __floats2bfloat162_rn(v0, v1);
        }
        // phase A: M[c][j][k] = sum_l e2[j,l] * W[(k*16+l)*128 + cb+c]  (f32 math)
        {
            ull a2[8];
            #pragma unroll
            for (int c2 = 0; c2 < 8; c2++) a2[c2] = 0ull;
            #pragma unroll
            for (int l = 0; l < 16; l++) {
                float e2v = s_e2t[l*32 + jA];
                ull e2p = pk2(e2v, e2v);
                const ulonglong2* Wp = (const ulonglong2*)(W + (size_t)(kA*16 + l)*128 + cb);
                ulonglong2 w01 = __ldg(Wp+0), w23 = __ldg(Wp+1), w45 = __ldg(Wp+2), w67 = __ldg(Wp+3);
                a2[0] = ffma2(e2p, w01.x, a2[0]); a2[1] = ffma2(e2p, w01.y, a2[1]);
                a2[2] = ffma2(e2p, w23.x, a2[2]); a2[3] = ffma2(e2p, w23.y, a2[3]);
                a2[4] = ffma2(e2p, w45.x, a2[4]); a2[5] = ffma2(e2p, w45.y, a2[5]);
                a2[6] = ffma2(e2p, w67.x, a2[6]); a2[7] = ffma2(e2p, w67.y, a2[7]);
            }
            #pragma unroll
            for (int c2 = 0; c2 < 8; c2++) {
                float lo, hi;
                upk2(a2[c2], lo, hi);
                s_M[((2*c2  )*32 + jA)*40 + kA] = __float2bfloat16_rn(lo);
                s_M[((2*c2+1)*32 + jA)*40 + kA] = __float2bfloat16_rn(hi);
            }
        }
        __syncthreads();
        // phase B
        #pragma unroll 1
        for (int cc = 0; cc < 16; cc++) {
            int c = cb + cc;
            const __nv_bfloat16* mrow = s_M + (cc*32 + j)*40;
            uint4 ma = *(const uint4*)(mrow);
            uint4 mb = *(const uint4*)(mrow + 8);
            float bg, bd;
            upk2(s_bgd[c], bg, bd);
            float t01[2];
            #pragma unroll
            for (int ii = 0; ii < 2; ii++) {
                __nv_bfloat162 ga = __floats2bfloat162_rn(0.f, 0.f);
                ga = __hfma2(e1h[ii][0], u2b(ma.x), ga);
                ga = __hfma2(e1h[ii][1], u2b(ma.y), ga);
                ga = __hfma2(e1h[ii][2], u2b(ma.z), ga);
                ga = __hfma2(e1h[ii][3], u2b(ma.w), ga);
                ga = __hfma2(e1h[ii][4], u2b(mb.x), ga);
                ga = __hfma2(e1h[ii][5], u2b(mb.y), ga);
                ga = __hfma2(e1h[ii][6], u2b(mb.z), ga);
                ga = __hfma2(e1h[ii][7], u2b(mb.w), ga);
                float g = __low2float(ga) + __high2float(ga) + bg;
                float sg = 0.5f + 0.5f*tanh_fast(0.5f*g);
                // 16-tap bf16 window: two LDS.128, near-uniform lanes
                const __nv_bfloat16* wrow = s_wdc + cc*72 + r0[ii];
                uint4 wa = *(const uint4*)(wrow);
                uint4 wb = *(const uint4*)(wrow + 8);
                __nv_bfloat162 da_ = __floats2bfloat162_rn(0.f, 0.f);
                da_ = __hfma2(rbfh[ii][0], u2b(wa.x), da_);
                da_ = __hfma2(rbfh[ii][1], u2b(wa.y), da_);
                da_ = __hfma2(rbfh[ii][2], u2b(wa.z), da_);
                da_ = __hfma2(rbfh[ii][3], u2b(wa.w), da_);
                da_ = __hfma2(rbfh[ii][4], u2b(wb.x), da_);
                da_ = __hfma2(rbfh[ii][5], u2b(wb.y), da_);
                da_ = __hfma2(rbfh[ii][6], u2b(wb.z), da_);
                da_ = __hfma2(rbfh[ii][7], u2b(wb.w), da_);
                float db = __low2float(da_) + __high2float(da_) + bd;
                t01[ii] = sg * db;
            }
            const ull* wt = s_wt2 + c*2;
            ull wt0 = wt[0], wt1 = wt[1];
            ull tp0 = pk2(t01[0], t01[0]);
            ull tp1 = pk2(t01[1], t01[1]);
            bacc[0][0] = ffma2(tp0, wt0, bacc[0][0]);
            bacc[0][1] = ffma2(tp0, wt1, bacc[0][1]);
            bacc[1][0] = ffma2(tp1, wt0, bacc[1][0]);
            bacc[1][1] = ffma2(tp1, wt1, bacc[1][1]);
        }
        __syncthreads();
    }
    #pragma unroll
    for (int ii = 0; ii < 2; ii++) {
        int i = ib + ii;
        float b0, b1, b2, b3;
        upk2(bacc[ii][0], b0, b1);
        upk2(bacc[ii][1], b2, b3);
        g_bias[(((size_t)n*NH + 0)*KK + i)*KK + j] = b0;
        g_bias[(((size_t)n*NH + 1)*KK + i)*KK + j] = b1;
        g_bias[(((size_t)n*NH + 2)*KK + i)*KK + j] = b2;
        g_bias[(((size_t)n*NH + 3)*KK + i)*KK + j] = b3;
    }
}

// ---------------- kernel: attention over K neighbors, per node ----------------
__global__ __launch_bounds__(128) void k_attn()
{
    int n = blockIdx.x;
    int tid = threadIdx.x;
    int h = tid >> 5, i = tid & 31;
    __shared__ float sk[KK*CZ];
    __shared__ float sv[KK*CZ];
    for (int p = tid; p < KK*CZ; p += 128) {
        int jj = p >> 7, c = p & 127;
        size_t base = (size_t)(n*KK + jj) * 512;
        sk[p] = g_qkvo[base + 128 + c];
        sv[p] = g_qkvo[base + 256 + c];
    }
    float qr[32];
    const float scale = 0.17677669529663687f;   // 1/sqrt(32)
    size_t erow = (size_t)(n*KK + i) * 512;
    #pragma unroll
    for (int d = 0; d < 32; d++) qr[d] = g_qkvo[erow + h*32 + d] * scale;
    __syncthreads();

    float s[32];
    float mx = -1e30f;
    const float* bp = g_bias + (((size_t)n*NH + h)*KK + i)*KK;
    #pragma unroll
    for (int jj = 0; jj < 32; jj++) {
        float acc = bp[jj];
        const float* kp = sk + jj*128 + h*32;
        #pragma unroll
        for (int d = 0; d < 32; d++) acc += qr[d] * kp[d];
        s[jj] = acc;
        mx = fmaxf(mx, acc);
    }
    float sum = 0.f;
    #pragma unroll
    for (int jj = 0; jj < 32; jj++) { s[jj] = __expf(s[jj] - mx); sum += s[jj]; }
    float inv = __fdividef(1.f, sum);
    float* op = g_og + (size_t)(n*KK + i)*CZ + h*32;
    const float* ogp = g_qkvo + erow + 384 + h*32;
    #pragma unroll
    for (int d = 0; d < 32; d++) {
        float acc = 0.f;
        const float* vp = sv + h*32 + d;
        #pragma unroll
        for (int jj = 0; jj < 32; jj++) acc += s[jj] * vp[jj*128];
        op[d] = acc * inv * ogp[d];
    }
}

// ---------------- launch ----------------
extern "C" void kernel_launch(void* const* d_in, const int* in_sizes, int n_in,
                              void* d_out, int out_size)
{
    const float* nf       = (const float*)d_in[0];
    const float* trans    = (const float*)d_in[1];
    const float* ef       = (const float*)d_in[2];
    const int*   ei       = (const int*)d_in[3];
    const float* w_left   = (const float*)d_in[4];
    const float* b_left   = (const float*)d_in[5];
    const float* w_right  = (const float*)d_in[6];
    const float* b_right  = (const float*)d_in[7];
    const float* w_bgate  = (const float*)d_in[8];
    const float* b_bgate  = (const float*)d_in[9];
    const float* w_dist   = (const float*)d_in[10];
    const float* b_dist   = (const float*)d_in[11];
    const float* w_tobias = (const float*)d_in[12];
    const float* ln_g     = (const float*)d_in[13];
    const float* ln_b     = (const float*)d_in[14];
    const float* w_q      = (const float*)d_in[15];
    const float* b_q      = (const float*)d_in[16];
    const float* w_kv     = (const float*)d_in[17];
    const float* b_kv     = (const float*)d_in[18];
    const float* w_out    = (const float*)d_in[19];
    const float* b_out    = (const float*)d_in[20];
    const float* w_ogate  = (const float*)d_in[21];
    const float* b_ogate  = (const float*)d_in[22];
    float* out = (float*)d_out;

    float *p_z, *p_qkvo, *p_og, *p_wcat, *p_bcat;
    cudaGetSymbolAddress((void**)&p_z,    g_z);
    cudaGetSymbolAddress((void**)&p_qkvo, g_qkvo);
    cudaGetSymbolAddress((void**)&p_og,   g_og);
    cudaGetSymbolAddress((void**)&p_wcat, g_wcat);
    cudaGetSymbolAddress((void**)&p_bcat, g_bcat);

    k_concat<<<128, 512>>>(w_q, b_q, w_kv, b_kv, w_ogate, b_ogate);
    k_nlr<<<NN, 32>>>(nf, w_left, b_left, w_right, b_right);
    k_ln<<<EE, 128>>>(ef, ln_g, ln_b);
    // k_tri is launch #4 (ncu -s 5 -c 1 captures it)
    k_tri<<<NN, 512>>>(ei, trans, w_bgate, b_bgate, w_dist, b_dist, w_tobias);
    {
        dim3 g(EE/128, 512/128);
        k_gemm_tc<<<g, 256>>>(p_z, p_wcat, p_qkvo, 512, p_bcat, 384);
    }
    k_attn<<<NN, 128>>>();
    {
        dim3 g(EE/128, 1);
        k_gemm_tc<<<g, 256>>>(p_og, w_out, out, 128, b_out, 1 << 30);
    }
}